// round 1
// baseline (speedup 1.0000x reference)
#include <cuda_runtime.h>
#include <math.h>

#define B_    16
#define N_    512
#define T_    96
#define FIN_  32
#define H_    128
#define FOUT_ 32

constexpr int       BN_TOT = B_ * N_;                       // 8192
constexpr long long M_TOT  = (long long)B_ * N_ * T_;       // 786432

// ---------------- scratch (static device globals; no allocation) ----------------
__device__ float g_adjn[N_ * N_];
__device__ float g_dis[N_];
__device__ float g_buf0[(size_t)M_TOT * H_];       // 402.7 MB
__device__ float g_buf1[(size_t)M_TOT * H_];       // 402.7 MB
__device__ float g_gi[(size_t)M_TOT * 3 * H_];     // 1.21 GB
__device__ float g_gh[(size_t)BN_TOT * 3 * H_];    // 12.6 MB
__device__ float g_h[(size_t)BN_TOT * H_];         // 4.2 MB

// ---------------- adjacency normalization ----------------
__global__ void adj_rowsum_k(const float* __restrict__ adj, float* __restrict__ dis) {
    int i = threadIdx.x;                     // 512 threads, 1 block
    float s = 1.0f;                          // +I diagonal
    for (int j = 0; j < N_; j++) s += adj[i * N_ + j];
    dis[i] = (s > 0.0f) ? rsqrtf(s) : 0.0f;
}

__global__ void adj_norm_k(const float* __restrict__ adj, const float* __restrict__ dis,
                           float* __restrict__ out) {
    int j = blockIdx.x * blockDim.x + threadIdx.x;   // col
    int i = blockIdx.y;                              // row
    float a = adj[i * N_ + j] + (i == j ? 1.0f : 0.0f);
    out[i * N_ + j] = dis[i] * a * dis[j];
}

// ---------------- generic tiled fp32 GEMM ----------------
// C[z] = op(A[z] @ B[z] + bias), row-major. TRANSB: B element (k,j) = B[j*K + k].
// MASKA: zero A elements exactly equal to -1.0f (missing-value mask).
template <int BM, int BN, int BK, int TM, int TN, bool TRANSB, bool MASKA, bool RELU>
__global__ void gemm_k(const float* __restrict__ A, const float* __restrict__ B,
                       const float* __restrict__ bias, float* __restrict__ C,
                       int M, int N, int K,
                       long long sA, long long sB, long long sC, int bias_mod) {
    A += (long long)blockIdx.z * sA;
    B += (long long)blockIdx.z * sB;
    C += (long long)blockIdx.z * sC;

    __shared__ float As[BK][BM + 1];
    __shared__ float Bs[BK][BN + 1];

    const int tid   = threadIdx.x;            // (BM/TM)*(BN/TN) == 256
    const int tcols = BN / TN;
    const int trow  = tid / tcols;
    const int tcol  = tid % tcols;
    const int row0  = blockIdx.y * BM;
    const int col0  = blockIdx.x * BN;

    float acc[TM][TN] = {};

    for (int k0 = 0; k0 < K; k0 += BK) {
        for (int i = tid; i < BM * BK; i += 256) {
            int r = i / BK, c = i % BK;
            int gr = row0 + r, gc = k0 + c;
            float v = (gr < M && gc < K) ? A[(long long)gr * K + gc] : 0.0f;
            if (MASKA && v == -1.0f) v = 0.0f;
            As[c][r] = v;
        }
        for (int i = tid; i < BK * BN; i += 256) {
            int r = i / BN, c = i % BN;
            int gr = k0 + r, gc = col0 + c;
            float v = 0.0f;
            if (gr < K && gc < N)
                v = TRANSB ? B[(long long)gc * K + gr] : B[(long long)gr * N + gc];
            Bs[r][c] = v;
        }
        __syncthreads();

        #pragma unroll
        for (int k = 0; k < BK; k++) {
            float a[TM], b[TN];
            #pragma unroll
            for (int m = 0; m < TM; m++) a[m] = As[k][trow * TM + m];
            #pragma unroll
            for (int n = 0; n < TN; n++) b[n] = Bs[k][tcol * TN + n];
            #pragma unroll
            for (int m = 0; m < TM; m++)
                #pragma unroll
                for (int n = 0; n < TN; n++)
                    acc[m][n] += a[m] * b[n];
        }
        __syncthreads();
    }

    #pragma unroll
    for (int m = 0; m < TM; m++) {
        int gr = row0 + trow * TM + m;
        if (gr >= M) continue;
        #pragma unroll
        for (int n = 0; n < TN; n++) {
            int gc = col0 + tcol * TN + n;
            if (gc >= N) continue;
            float v = acc[m][n];
            if (bias) v += bias[gc % bias_mod];
            if (RELU) v = fmaxf(v, 0.0f);
            C[(long long)gr * N + gc] = v;
        }
    }
}

// ---------------- GRU ----------------
__global__ void zero_k(float* __restrict__ p, int n) {
    int i = blockIdx.x * blockDim.x + threadIdx.x;
    if (i < n) p[i] = 0.0f;
}

// gates + state update + store gru_out[b,n,t,:]
__global__ void gru_step_k(const float* __restrict__ gi, const float* __restrict__ gh,
                           float* __restrict__ h, float* __restrict__ out, int t) {
    int idx = blockIdx.x * blockDim.x + threadIdx.x;     // BN_TOT * H_
    int i = idx >> 7;          // bn index
    int c = idx & 127;         // hidden channel
    const float* gip = gi + ((long long)i * T_ + t) * (3 * H_);
    const float* ghp = gh + (long long)i * (3 * H_);

    float ir = gip[c], iz = gip[c + H_], in = gip[c + 2 * H_];
    float hr = ghp[c], hz = ghp[c + H_], hn = ghp[c + 2 * H_];

    float r = 1.0f / (1.0f + expf(-(ir + hr)));
    float z = 1.0f / (1.0f + expf(-(iz + hz)));
    float n = tanhf(in + r * hn);

    float hprev = h[(long long)i * H_ + c];
    float hnew  = (1.0f - z) * n + z * hprev;

    h[(long long)i * H_ + c] = hnew;
    out[((long long)i * T_ + t) * H_ + c] = hnew;
}

// ---------------- launch ----------------
extern "C" void kernel_launch(void* const* d_in, const int* in_sizes, int n_in,
                              void* d_out, int out_size) {
    const float* x     = (const float*)d_in[0];
    const float* adj   = (const float*)d_in[1];
    const float* gc_w0 = (const float*)d_in[2];
    const float* gc_b0 = (const float*)d_in[3];
    const float* gc_w1 = (const float*)d_in[4];
    const float* gc_b1 = (const float*)d_in[5];
    const float* w_ih  = (const float*)d_in[6];
    const float* w_hh  = (const float*)d_in[7];
    const float* b_ih  = (const float*)d_in[8];
    const float* b_hh  = (const float*)d_in[9];
    const float* w_fc  = (const float*)d_in[10];
    const float* b_fc  = (const float*)d_in[11];
    float* out = (float*)d_out;

    float *adjn, *dis, *buf0, *buf1, *gi, *gh, *h;
    cudaGetSymbolAddress((void**)&adjn, g_adjn);
    cudaGetSymbolAddress((void**)&dis,  g_dis);
    cudaGetSymbolAddress((void**)&buf0, g_buf0);
    cudaGetSymbolAddress((void**)&buf1, g_buf1);
    cudaGetSymbolAddress((void**)&gi,   g_gi);
    cudaGetSymbolAddress((void**)&gh,   g_gh);
    cudaGetSymbolAddress((void**)&h,    g_h);

    const int M = (int)M_TOT;   // 786432

    // 1) adjacency normalization
    adj_rowsum_k<<<1, N_>>>(adj, dis);
    adj_norm_k<<<dim3(N_ / 256, N_), 256>>>(adj, dis, adjn);

    // 2) GCN layer 0: support = mask(x) @ gc_w0
    gemm_k<64, 64, 16, 4, 4, false, true, false>
        <<<dim3(H_ / 64, M / 64), 256>>>(x, gc_w0, nullptr, buf0,
                                         M, H_, FIN_, 0, 0, 0, 1);
    // A-hop 0: h1 = relu(adj_norm @ support + b0), batched over B
    gemm_k<64, 64, 16, 4, 4, false, false, true>
        <<<dim3((T_ * H_) / 64, N_ / 64, B_), 256>>>(adjn, buf0, gc_b0, buf1,
            N_, T_ * H_, N_, 0, (long long)N_ * T_ * H_, (long long)N_ * T_ * H_, H_);

    // 3) GCN layer 1: support = h1 @ gc_w1  (mask is a numeric no-op post-ReLU)
    gemm_k<64, 64, 16, 4, 4, false, false, false>
        <<<dim3(H_ / 64, M / 64), 256>>>(buf1, gc_w1, nullptr, buf0,
                                         M, H_, H_, 0, 0, 0, 1);
    // A-hop 1: h2 = relu(adj_norm @ support + b1)
    gemm_k<64, 64, 16, 4, 4, false, false, true>
        <<<dim3((T_ * H_) / 64, N_ / 64, B_), 256>>>(adjn, buf0, gc_b1, buf1,
            N_, T_ * H_, N_, 0, (long long)N_ * T_ * H_, (long long)N_ * T_ * H_, H_);

    // 4) GRU input gates for ALL timesteps: GI = h2 @ w_ih^T + b_ih
    gemm_k<64, 64, 16, 4, 4, true, false, false>
        <<<dim3((3 * H_) / 64, M / 64), 256>>>(buf1, w_ih, b_ih, gi,
                                               M, 3 * H_, H_, 0, 0, 0, 3 * H_);

    // 5) recurrence
    zero_k<<<(BN_TOT * H_) / 256, 256>>>(h, BN_TOT * H_);
    for (int t = 0; t < T_; t++) {
        gemm_k<64, 64, 16, 4, 4, true, false, false>
            <<<dim3((3 * H_) / 64, BN_TOT / 64), 256>>>(h, w_hh, b_hh, gh,
                                                        BN_TOT, 3 * H_, H_, 0, 0, 0, 3 * H_);
        gru_step_k<<<(BN_TOT * H_) / 256, 256>>>(gi, gh, h, buf0, t);
    }

    // 6) FC: out = gru_out @ w_fc + b_fc
    gemm_k<64, 64, 16, 4, 4, false, false, false>
        <<<dim3(1, M / 64), 256>>>(buf0, w_fc, b_fc, out,
                                   M, FOUT_, H_, 0, 0, 0, FOUT_);
}

// round 4
// speedup vs baseline: 2.9753x; 2.9753x over previous
#include <cuda_runtime.h>
#include <math.h>

#define B_    16
#define N_    512
#define T_    96
#define FIN_  32
#define H_    128
#define FOUT_ 32

constexpr int       BN_TOT = B_ * N_;                       // 8192
constexpr long long M_TOT  = (long long)B_ * N_ * T_;       // 786432

using u64_t = unsigned long long;

// ---------------- scratch (static device globals; no allocation) ----------------
__device__ float g_adjn[N_ * N_];
__device__ float g_dis[N_];
__device__ float g_buf0[(size_t)M_TOT * H_];       // 402.7 MB
__device__ float g_buf1[(size_t)M_TOT * H_];       // 402.7 MB
__device__ float g_gi[(size_t)M_TOT * 3 * H_];     // 1.21 GB

// ---------------- f32x2 helpers ----------------
__device__ __forceinline__ u64_t bcast2(float x) {
    u64_t r; asm("mov.b64 %0, {%1,%2};" : "=l"(r) : "f"(x), "f"(x)); return r;
}
__device__ __forceinline__ u64_t lo2(const float4& v) {
    u64_t r; asm("mov.b64 %0, {%1,%2};" : "=l"(r) : "f"(v.x), "f"(v.y)); return r;
}
__device__ __forceinline__ u64_t hi2(const float4& v) {
    u64_t r; asm("mov.b64 %0, {%1,%2};" : "=l"(r) : "f"(v.z), "f"(v.w)); return r;
}
__device__ __forceinline__ void fma2(u64_t& d, u64_t a, u64_t b) {
    asm("fma.rn.f32x2 %0, %1, %2, %0;" : "+l"(d) : "l"(a), "l"(b));
}
__device__ __forceinline__ float2 unpack2(u64_t v) {
    float2 r; asm("mov.b64 {%0,%1}, %2;" : "=f"(r.x), "=f"(r.y) : "l"(v)); return r;
}

// ---------------- FMA-only activations (no MUFU) ----------------
__device__ __forceinline__ float frcp_fast(float d) {
    float r = __uint_as_float(0x7EF311C3u - __float_as_uint(d));
    r = r * (2.0f - d * r);
    r = r * (2.0f - d * r);
    return r;
}
__device__ __forceinline__ float tanh_fast(float x) {
    x = fminf(7.90531f, fmaxf(-7.90531f, x));
    float x2 = x * x;
    float p = -2.76076847742355e-16f;
    p = fmaf(p, x2, 2.00018790482477e-13f);
    p = fmaf(p, x2, -8.60467152213735e-11f);
    p = fmaf(p, x2, 5.12229709037114e-08f);
    p = fmaf(p, x2, 1.48572235717979e-05f);
    p = fmaf(p, x2, 6.37261928875436e-04f);
    p = fmaf(p, x2, 4.89352455891786e-03f);
    p = p * x;
    float q = 1.19825839466702e-06f;
    q = fmaf(q, x2, 1.18534705686654e-04f);
    q = fmaf(q, x2, 2.26843463243900e-03f);
    q = fmaf(q, x2, 4.89352518554385e-03f);
    return p * frcp_fast(q);
}
__device__ __forceinline__ float sigmoid_fast(float x) {
    return 0.5f + 0.5f * tanh_fast(0.5f * x);
}

// ---------------- adjacency normalization ----------------
__global__ void adj_rowsum_k(const float* __restrict__ adj, float* __restrict__ dis) {
    int i = threadIdx.x;
    float s = 1.0f;
    for (int j = 0; j < N_; j++) s += adj[i * N_ + j];
    dis[i] = (s > 0.0f) ? rsqrtf(s) : 0.0f;
}
__global__ void adj_norm_k(const float* __restrict__ adj, const float* __restrict__ dis,
                           float* __restrict__ out) {
    int j = blockIdx.x * blockDim.x + threadIdx.x;
    int i = blockIdx.y;
    float a = adj[i * N_ + j] + (i == j ? 1.0f : 0.0f);
    out[i * N_ + j] = dis[i] * a * dis[j];
}

// ---------------- tiled fp32 GEMM with FFMA2 ----------------
// C[z] = op(A @ B[z] + bias).  A:[M,K] shared across z.  TRANSB: B is [N,K].
// All dims are multiples of the tile sizes for every call below.
template <int BM, int BN, int BK, int TM, int TN, bool TRANSB, bool MASKB, bool RELU, bool BIAS>
__global__ void __launch_bounds__((BM / TM) * (BN / TN))
gemm_k(const float* __restrict__ A, const float* __restrict__ B,
       const float* __restrict__ bias, float* __restrict__ C,
       int M, int N, int K, long long sB, long long sC, int bias_mod) {
    constexpr int THREADS = (BM / TM) * (BN / TN);
    constexpr int MCH = TM / 4, NCH = TN / 4;
    constexpr int RS = BM / MCH, CS = BN / NCH;

    B += (long long)blockIdx.z * sB;
    C += (long long)blockIdx.z * sC;

    __shared__ float As[BK][BM + 4];
    __shared__ float Bs[BK][BN + 4];

    const int tid   = threadIdx.x;
    const int tcols = BN / TN;
    const int trow  = tid / tcols;
    const int tcol  = tid % tcols;
    const long long row0 = (long long)blockIdx.y * BM;
    const int col0 = blockIdx.x * BN;

    u64_t acc[TM][TN / 2];
    #pragma unroll
    for (int m = 0; m < TM; m++)
        #pragma unroll
        for (int p = 0; p < TN / 2; p++) acc[m][p] = 0ULL;

    for (int k0 = 0; k0 < K; k0 += BK) {
        #pragma unroll
        for (int i = tid; i < BM * BK / 4; i += THREADS) {
            int r = i / (BK / 4), kk = (i % (BK / 4)) * 4;
            float4 v = *(const float4*)&A[(row0 + r) * K + k0 + kk];
            As[kk + 0][r] = v.x; As[kk + 1][r] = v.y;
            As[kk + 2][r] = v.z; As[kk + 3][r] = v.w;
        }
        if (!TRANSB) {
            #pragma unroll
            for (int i = tid; i < BK * BN / 4; i += THREADS) {
                int r = i / (BN / 4), c = (i % (BN / 4)) * 4;
                float4 v = *(const float4*)&B[(long long)(k0 + r) * N + col0 + c];
                if (MASKB) {
                    if (v.x == -1.0f) v.x = 0.0f;
                    if (v.y == -1.0f) v.y = 0.0f;
                    if (v.z == -1.0f) v.z = 0.0f;
                    if (v.w == -1.0f) v.w = 0.0f;
                }
                *(float4*)&Bs[r][c] = v;
            }
        } else {
            #pragma unroll
            for (int i = tid; i < BN * BK / 4; i += THREADS) {
                int c = i / (BK / 4), kk = (i % (BK / 4)) * 4;
                float4 v = *(const float4*)&B[(long long)(col0 + c) * K + k0 + kk];
                Bs[kk + 0][c] = v.x; Bs[kk + 1][c] = v.y;
                Bs[kk + 2][c] = v.z; Bs[kk + 3][c] = v.w;
            }
        }
        __syncthreads();

        #pragma unroll 4
        for (int k = 0; k < BK; k++) {
            u64_t av[TM];
            #pragma unroll
            for (int i = 0; i < MCH; i++) {
                float4 a = *(const float4*)&As[k][i * RS + trow * 4];
                av[i * 4 + 0] = bcast2(a.x); av[i * 4 + 1] = bcast2(a.y);
                av[i * 4 + 2] = bcast2(a.z); av[i * 4 + 3] = bcast2(a.w);
            }
            u64_t bp[TN / 2];
            #pragma unroll
            for (int j = 0; j < NCH; j++) {
                float4 b = *(const float4*)&Bs[k][j * CS + tcol * 4];
                bp[j * 2 + 0] = lo2(b);
                bp[j * 2 + 1] = hi2(b);
            }
            #pragma unroll
            for (int m = 0; m < TM; m++)
                #pragma unroll
                for (int p = 0; p < TN / 2; p++)
                    fma2(acc[m][p], av[m], bp[p]);
        }
        __syncthreads();
    }

    #pragma unroll
    for (int i = 0; i < MCH; i++) {
        #pragma unroll
        for (int mm = 0; mm < 4; mm++) {
            long long row = row0 + i * RS + trow * 4 + mm;
            int m = i * 4 + mm;
            #pragma unroll
            for (int j = 0; j < NCH; j++) {
                int col = col0 + j * CS + tcol * 4;
                float2 lo = unpack2(acc[m][j * 2]);
                float2 hi = unpack2(acc[m][j * 2 + 1]);
                float4 v = make_float4(lo.x, lo.y, hi.x, hi.y);
                if (BIAS) {
                    int cb = col % bias_mod;
                    v.x += bias[cb]; v.y += bias[cb + 1];
                    v.z += bias[cb + 2]; v.w += bias[cb + 3];
                }
                if (RELU) {
                    v.x = fmaxf(v.x, 0.f); v.y = fmaxf(v.y, 0.f);
                    v.z = fmaxf(v.z, 0.f); v.w = fmaxf(v.w, 0.f);
                }
                *(float4*)&C[row * N + col] = v;
            }
        }
    }
}

// ---------------- fused persistent GRU ----------------
// One launch for all 96 timesteps. Block = 256 threads handles 64 (b,n) rows.
// smem: ws[k][j] = w_hh[j][k]  (128 x 384), hs[64][128].
// Thread (rg,cg): rows rg*8..+7, channels cg*4..+3, all 3 gates.
__global__ void __launch_bounds__(256, 1)
gru_fused_k(const float* __restrict__ gi, const float* __restrict__ w_hh,
            const float* __restrict__ b_hh, float* __restrict__ out) {
    extern __shared__ float sm[];
    float* ws = sm;                 // 128*384
    float* hs = sm + 128 * 384;     // 64*128

    const int tid = threadIdx.x;
    const int rg = tid >> 5, cg = tid & 31;
    const int r0 = rg * 8, c0 = cg * 4;
    const long long bn0 = (long long)blockIdx.x * 64;

    // load w_hh transposed into smem
    for (int i = tid; i < 384 * 32; i += 256) {     // 12288 float4s
        int j = i / 32, k4 = (i % 32) * 4;
        float4 v = *(const float4*)&w_hh[j * 128 + k4];
        ws[(k4 + 0) * 384 + j] = v.x; ws[(k4 + 1) * 384 + j] = v.y;
        ws[(k4 + 2) * 384 + j] = v.z; ws[(k4 + 3) * 384 + j] = v.w;
    }
    for (int i = tid; i < 64 * 128; i += 256) hs[i] = 0.0f;

    float bh_r[4], bh_z[4], bh_n[4];
    #pragma unroll
    for (int u = 0; u < 4; u++) {
        bh_r[u] = b_hh[c0 + u];
        bh_z[u] = b_hh[128 + c0 + u];
        bh_n[u] = b_hh[256 + c0 + u];
    }
    __syncthreads();

    for (int t = 0; t < T_; t++) {
        u64_t acc[8][6];
        #pragma unroll
        for (int i = 0; i < 8; i++)
            #pragma unroll
            for (int p = 0; p < 6; p++) acc[i][p] = 0ULL;

        #pragma unroll 2
        for (int k = 0; k < 128; k++) {
            u64_t av[8];
            #pragma unroll
            for (int i = 0; i < 8; i++) av[i] = bcast2(hs[(r0 + i) * 128 + k]);
            const float* wrow = &ws[k * 384];
            float4 w0 = *(const float4*)&wrow[c0];
            float4 w1 = *(const float4*)&wrow[128 + c0];
            float4 w2 = *(const float4*)&wrow[256 + c0];
            u64_t wp[6] = {lo2(w0), hi2(w0), lo2(w1), hi2(w1), lo2(w2), hi2(w2)};
            #pragma unroll
            for (int i = 0; i < 8; i++)
                #pragma unroll
                for (int p = 0; p < 6; p++)
                    fma2(acc[i][p], av[i], wp[p]);
        }
        __syncthreads();

        #pragma unroll
        for (int i = 0; i < 8; i++) {
            long long row = bn0 + r0 + i;
            const float* gp = gi + (row * T_ + t) * (3 * H_);
            float4 xr = *(const float4*)(gp + c0);
            float4 xz = *(const float4*)(gp + 128 + c0);
            float4 xn = *(const float4*)(gp + 256 + c0);
            float2 a0 = unpack2(acc[i][0]), a1 = unpack2(acc[i][1]);
            float2 a2 = unpack2(acc[i][2]), a3 = unpack2(acc[i][3]);
            float2 a4 = unpack2(acc[i][4]), a5 = unpack2(acc[i][5]);
            float hr[4] = {a0.x, a0.y, a1.x, a1.y};
            float hz[4] = {a2.x, a2.y, a3.x, a3.y};
            float hn[4] = {a4.x, a4.y, a5.x, a5.y};
            float xrv[4] = {xr.x, xr.y, xr.z, xr.w};
            float xzv[4] = {xz.x, xz.y, xz.z, xz.w};
            float xnv[4] = {xn.x, xn.y, xn.z, xn.w};
            float hv[4];
            #pragma unroll
            for (int u = 0; u < 4; u++) {
                float rr = sigmoid_fast(xrv[u] + hr[u] + bh_r[u]);
                float zz = sigmoid_fast(xzv[u] + hz[u] + bh_z[u]);
                float nn = tanh_fast(xnv[u] + rr * (hn[u] + bh_n[u]));
                float hp = hs[(r0 + i) * 128 + c0 + u];
                hv[u] = fmaf(zz, hp - nn, nn);
            }
            float4 o = make_float4(hv[0], hv[1], hv[2], hv[3]);
            *(float4*)&hs[(r0 + i) * 128 + c0] = o;
            *(float4*)&out[(row * T_ + t) * H_ + c0] = o;
        }
        __syncthreads();
    }
}

// ---------------- launch ----------------
extern "C" void kernel_launch(void* const* d_in, const int* in_sizes, int n_in,
                              void* d_out, int out_size) {
    const float* x     = (const float*)d_in[0];
    const float* adj   = (const float*)d_in[1];
    const float* gc_w0 = (const float*)d_in[2];
    const float* gc_b0 = (const float*)d_in[3];
    const float* gc_w1 = (const float*)d_in[4];
    const float* gc_b1 = (const float*)d_in[5];
    const float* w_ih  = (const float*)d_in[6];
    const float* w_hh  = (const float*)d_in[7];
    const float* b_ih  = (const float*)d_in[8];
    const float* b_hh  = (const float*)d_in[9];
    const float* w_fc  = (const float*)d_in[10];
    const float* b_fc  = (const float*)d_in[11];
    float* out = (float*)d_out;

    float *adjn, *dis, *buf0, *buf1, *gi;
    cudaGetSymbolAddress((void**)&adjn, g_adjn);
    cudaGetSymbolAddress((void**)&dis,  g_dis);
    cudaGetSymbolAddress((void**)&buf0, g_buf0);
    cudaGetSymbolAddress((void**)&buf1, g_buf1);
    cudaGetSymbolAddress((void**)&gi,   g_gi);

    const int M = (int)M_TOT;   // 786432

    // 1) adjacency normalization
    adj_rowsum_k<<<1, N_>>>(adj, dis);
    adj_norm_k<<<dim3(N_ / 256, N_), 256>>>(adj, dis, adjn);

    // 2) A-hop FIRST on raw (masked) x: Y0 = adjn @ mask(x)   [per batch, N=3072]
    gemm_k<128, 128, 16, 8, 8, false, true, false, false>
        <<<dim3((T_ * FIN_) / 128, N_ / 128, B_), 256>>>(
            adjn, x, nullptr, buf0, N_, T_ * FIN_, N_,
            (long long)N_ * T_ * FIN_, (long long)N_ * T_ * FIN_, 1);

    // 3) h1 = relu(Y0 @ gc_w0 + b0)
    gemm_k<128, 128, 16, 8, 8, false, false, true, true>
        <<<dim3(1, M / 128), 256>>>(buf0, gc_w0, gc_b0, buf1,
                                    M, H_, FIN_, 0, 0, H_);

    // 4) S1 = h1 @ gc_w1
    gemm_k<128, 128, 16, 8, 8, false, false, false, false>
        <<<dim3(1, M / 128), 256>>>(buf1, gc_w1, nullptr, buf0,
                                    M, H_, H_, 0, 0, 1);

    // 5) h2 = relu(adjn @ S1 + b1)   [per batch, N=12288]
    gemm_k<128, 128, 16, 8, 8, false, false, true, true>
        <<<dim3((T_ * H_) / 128, N_ / 128, B_), 256>>>(
            adjn, buf0, gc_b1, buf1, N_, T_ * H_, N_,
            (long long)N_ * T_ * H_, (long long)N_ * T_ * H_, H_);

    // 6) GI = h2 @ w_ih^T + b_ih
    gemm_k<128, 128, 16, 8, 8, true, false, false, true>
        <<<dim3((3 * H_) / 128, M / 128), 256>>>(buf1, w_ih, b_ih, gi,
                                                 M, 3 * H_, H_, 0, 0, 3 * H_);

    // 7) fused GRU recurrence (single persistent launch, all timesteps)
    constexpr int GRU_SMEM = (128 * 384 + 64 * 128) * 4;   // 229376 bytes
    cudaFuncSetAttribute(gru_fused_k, cudaFuncAttributeMaxDynamicSharedMemorySize, GRU_SMEM);
    gru_fused_k<<<BN_TOT / 64, 256, GRU_SMEM>>>(gi, w_hh, b_hh, buf0);

    // 8) FC: out = gru_out @ w_fc + b_fc
    gemm_k<128, 32, 16, 8, 4, false, false, false, true>
        <<<dim3(1, M / 128), 128>>>(buf0, w_fc, b_fc, out,
                                    M, FOUT_, H_, 0, 0, FOUT_);
}

// round 8
// speedup vs baseline: 3.3432x; 1.1236x over previous
#include <cuda_runtime.h>
#include <cuda_bf16.h>
#include <cstdint>
#include <math.h>

#define B_    16
#define N_    512
#define T_    96
#define FIN_  32
#define H_    128
#define FOUT_ 32

constexpr int       BN_TOT = B_ * N_;                       // 8192
constexpr long long M_TOT  = (long long)B_ * N_ * T_;       // 786432

using u64_t = unsigned long long;

// ---------------- pooled scratch (host .bss shadow must stay < 2 GiB) ----------------
// Lifetime-aliased regions (bytes):
//   [0, 201326592)            s1t_hi   (steps 4b..5)     } overlapped by gi (step 6..7)
//   [201326592, 402653184)    s1t_lo   (steps 4b..5)     }
//   [402653184, 805306368)    h1 fp32  (steps 3..4)      }
//   [805306368, 1207959552)   Y0/S1 fp32 (steps 2..4b)   }
//   [0, 1207959552)           gi fp32  (steps 6..7)
//   [1207959552, 1409286144)  h2_hi    (steps 5..6)      } overlapped by gru_out (7..8)
//   [1409286144, 1610612736)  h2_lo    (steps 5..6)      }
//   [1207959552, 1610612736)  gru_out fp32 (steps 7..8)
constexpr size_t POOL_BYTES = 1610612736ULL;   // 1.5 GiB
__device__ __align__(128) unsigned char g_pool[POOL_BYTES];

__device__ float g_adjn[N_ * N_];
__device__ __nv_bfloat16 g_adjn_hi[N_ * N_];
__device__ __nv_bfloat16 g_adjn_lo[N_ * N_];
__device__ float g_dis[N_];
__device__ __nv_bfloat16 g_wih_hi[3 * H_ * H_];
__device__ __nv_bfloat16 g_wih_lo[3 * H_ * H_];

// ---------------- f32x2 helpers ----------------
__device__ __forceinline__ u64_t bcast2(float x) {
    u64_t r; asm("mov.b64 %0, {%1,%2};" : "=l"(r) : "f"(x), "f"(x)); return r;
}
__device__ __forceinline__ u64_t lo2(const float4& v) {
    u64_t r; asm("mov.b64 %0, {%1,%2};" : "=l"(r) : "f"(v.x), "f"(v.y)); return r;
}
__device__ __forceinline__ u64_t hi2(const float4& v) {
    u64_t r; asm("mov.b64 %0, {%1,%2};" : "=l"(r) : "f"(v.z), "f"(v.w)); return r;
}
__device__ __forceinline__ void fma2(u64_t& d, u64_t a, u64_t b) {
    asm("fma.rn.f32x2 %0, %1, %2, %0;" : "+l"(d) : "l"(a), "l"(b));
}
__device__ __forceinline__ float2 unpack2(u64_t v) {
    float2 r; asm("mov.b64 {%0,%1}, %2;" : "=f"(r.x), "=f"(r.y) : "l"(v)); return r;
}

// ---------------- FMA-only activations (no MUFU) ----------------
__device__ __forceinline__ float frcp_fast(float d) {
    float r = __uint_as_float(0x7EF311C3u - __float_as_uint(d));
    r = r * (2.0f - d * r);
    r = r * (2.0f - d * r);
    return r;
}
__device__ __forceinline__ float tanh_fast(float x) {
    x = fminf(7.90531f, fmaxf(-7.90531f, x));
    float x2 = x * x;
    float p = -2.76076847742355e-16f;
    p = fmaf(p, x2, 2.00018790482477e-13f);
    p = fmaf(p, x2, -8.60467152213735e-11f);
    p = fmaf(p, x2, 5.12229709037114e-08f);
    p = fmaf(p, x2, 1.48572235717979e-05f);
    p = fmaf(p, x2, 6.37261928875436e-04f);
    p = fmaf(p, x2, 4.89352455891786e-03f);
    p = p * x;
    float q = 1.19825839466702e-06f;
    q = fmaf(q, x2, 1.18534705686654e-04f);
    q = fmaf(q, x2, 2.26843463243900e-03f);
    q = fmaf(q, x2, 4.89352518554385e-03f);
    return p * frcp_fast(q);
}
__device__ __forceinline__ float sigmoid_fast(float x) {
    return 0.5f + 0.5f * tanh_fast(0.5f * x);
}

// ---------------- mma.sync helpers (sm_80+ path, works on plain sm_100) ----------------
__device__ __forceinline__ uint32_t smem_u32(const void* p) {
    uint32_t a;
    asm("{ .reg .u64 t; cvta.to.shared.u64 t, %1; cvt.u32.u64 %0, t; }" : "=r"(a) : "l"(p));
    return a;
}
__device__ __forceinline__ void ldm_x4(uint32_t& r0, uint32_t& r1, uint32_t& r2, uint32_t& r3,
                                       uint32_t addr) {
    asm volatile("ldmatrix.sync.aligned.m8n8.x4.shared.b16 {%0,%1,%2,%3}, [%4];"
                 : "=r"(r0), "=r"(r1), "=r"(r2), "=r"(r3) : "r"(addr));
}
__device__ __forceinline__ void ldm_x2(uint32_t& r0, uint32_t& r1, uint32_t addr) {
    asm volatile("ldmatrix.sync.aligned.m8n8.x2.shared.b16 {%0,%1}, [%2];"
                 : "=r"(r0), "=r"(r1) : "r"(addr));
}
__device__ __forceinline__ void mma_bf16(float* c, const uint32_t* a, const uint32_t* b) {
    asm volatile("mma.sync.aligned.m16n8k16.row.col.f32.bf16.bf16.f32 "
                 "{%0,%1,%2,%3}, {%4,%5,%6,%7}, {%8,%9}, {%0,%1,%2,%3};"
                 : "+f"(c[0]), "+f"(c[1]), "+f"(c[2]), "+f"(c[3])
                 : "r"(a[0]), "r"(a[1]), "r"(a[2]), "r"(a[3]), "r"(b[0]), "r"(b[1]));
}

// ---------------- adjacency normalization ----------------
__global__ void adj_rowsum_k(const float* __restrict__ adj, float* __restrict__ dis) {
    int i = threadIdx.x;
    float s = 1.0f;
    for (int j = 0; j < N_; j++) s += adj[i * N_ + j];
    dis[i] = (s > 0.0f) ? rsqrtf(s) : 0.0f;
}
__global__ void adj_norm_k(const float* __restrict__ adj, const float* __restrict__ dis,
                           float* __restrict__ out,
                           __nv_bfloat16* __restrict__ ohi, __nv_bfloat16* __restrict__ olo) {
    int j = blockIdx.x * blockDim.x + threadIdx.x;
    int i = blockIdx.y;
    float a = adj[i * N_ + j] + (i == j ? 1.0f : 0.0f);
    float v = dis[i] * a * dis[j];
    out[i * N_ + j] = v;
    __nv_bfloat16 h = __float2bfloat16(v);
    ohi[i * N_ + j] = h;
    olo[i * N_ + j] = __float2bfloat16(v - __bfloat162float(h));
}

// ---------------- elementwise fp32 -> bf16 hi/lo split ----------------
__global__ void split_k(const float* __restrict__ src, __nv_bfloat16* __restrict__ hi,
                        __nv_bfloat16* __restrict__ lo, int n) {
    int i = blockIdx.x * blockDim.x + threadIdx.x;
    if (i >= n) return;
    float v = src[i];
    __nv_bfloat16 h = __float2bfloat16(v);
    hi[i] = h;
    lo[i] = __float2bfloat16(v - __bfloat162float(h));
}

// ---------------- transpose + split: S1[b][node][c] -> S1T[b][c][node] bf16 hi/lo ----------------
__global__ void transpose_split_k(const float* __restrict__ src,
                                  __nv_bfloat16* __restrict__ hi, __nv_bfloat16* __restrict__ lo) {
    __shared__ float tile[32][33];
    const int b = blockIdx.z;
    const long long cBase = (long long)blockIdx.x * 32;   // c in [0,12288)
    const long long nBase = (long long)blockIdx.y * 32;   // node in [0,512)
    const float* s = src + (long long)b * N_ * (T_ * H_);
    #pragma unroll
    for (int i = threadIdx.y; i < 32; i += 8)
        tile[i][threadIdx.x] = s[(nBase + i) * (T_ * H_) + cBase + threadIdx.x];
    __syncthreads();
    const long long ob = (long long)b * (T_ * H_) * N_;
    #pragma unroll
    for (int i = threadIdx.y; i < 32; i += 8) {
        float v = tile[threadIdx.x][i];                    // [node=nBase+tx][c=cBase+i]
        __nv_bfloat16 h = __float2bfloat16(v);
        long long o = ob + (cBase + i) * N_ + nBase + threadIdx.x;
        hi[o] = h;
        lo[o] = __float2bfloat16(v - __bfloat162float(h));
    }
}

// ---------------- tiled fp32 GEMM with FFMA2 (SIMT; steps 2,3,4, FC) ----------------
template <int BM, int BN, int BK, int TM, int TN, bool TRANSB, bool MASKB, bool RELU, bool BIAS>
__global__ void __launch_bounds__((BM / TM) * (BN / TN))
gemm_k(const float* __restrict__ A, const float* __restrict__ B,
       const float* __restrict__ bias, float* __restrict__ C,
       int M, int N, int K, long long sB, long long sC, int bias_mod) {
    constexpr int THREADS = (BM / TM) * (BN / TN);
    constexpr int MCH = TM / 4, NCH = TN / 4;
    constexpr int RS = BM / MCH, CS = BN / NCH;

    B += (long long)blockIdx.z * sB;
    C += (long long)blockIdx.z * sC;

    __shared__ float As[BK][BM + 4];
    __shared__ float Bs[BK][BN + 4];

    const int tid   = threadIdx.x;
    const int tcols = BN / TN;
    const int trow  = tid / tcols;
    const int tcol  = tid % tcols;
    const long long row0 = (long long)blockIdx.y * BM;
    const int col0 = blockIdx.x * BN;

    u64_t acc[TM][TN / 2];
    #pragma unroll
    for (int m = 0; m < TM; m++)
        #pragma unroll
        for (int p = 0; p < TN / 2; p++) acc[m][p] = 0ULL;

    for (int k0 = 0; k0 < K; k0 += BK) {
        #pragma unroll
        for (int i = tid; i < BM * BK / 4; i += THREADS) {
            int r = i / (BK / 4), kk = (i % (BK / 4)) * 4;
            float4 v = *(const float4*)&A[(row0 + r) * K + k0 + kk];
            As[kk + 0][r] = v.x; As[kk + 1][r] = v.y;
            As[kk + 2][r] = v.z; As[kk + 3][r] = v.w;
        }
        if (!TRANSB) {
            #pragma unroll
            for (int i = tid; i < BK * BN / 4; i += THREADS) {
                int r = i / (BN / 4), c = (i % (BN / 4)) * 4;
                float4 v = *(const float4*)&B[(long long)(k0 + r) * N + col0 + c];
                if (MASKB) {
                    if (v.x == -1.0f) v.x = 0.0f;
                    if (v.y == -1.0f) v.y = 0.0f;
                    if (v.z == -1.0f) v.z = 0.0f;
                    if (v.w == -1.0f) v.w = 0.0f;
                }
                *(float4*)&Bs[r][c] = v;
            }
        } else {
            #pragma unroll
            for (int i = tid; i < BN * BK / 4; i += THREADS) {
                int c = i / (BK / 4), kk = (i % (BK / 4)) * 4;
                float4 v = *(const float4*)&B[(long long)(col0 + c) * K + k0 + kk];
                Bs[kk + 0][c] = v.x; Bs[kk + 1][c] = v.y;
                Bs[kk + 2][c] = v.z; Bs[kk + 3][c] = v.w;
            }
        }
        __syncthreads();

        #pragma unroll 4
        for (int k = 0; k < BK; k++) {
            u64_t av[TM];
            #pragma unroll
            for (int i = 0; i < MCH; i++) {
                float4 a = *(const float4*)&As[k][i * RS + trow * 4];
                av[i * 4 + 0] = bcast2(a.x); av[i * 4 + 1] = bcast2(a.y);
                av[i * 4 + 2] = bcast2(a.z); av[i * 4 + 3] = bcast2(a.w);
            }
            u64_t bp[TN / 2];
            #pragma unroll
            for (int j = 0; j < NCH; j++) {
                float4 b = *(const float4*)&Bs[k][j * CS + tcol * 4];
                bp[j * 2 + 0] = lo2(b);
                bp[j * 2 + 1] = hi2(b);
            }
            #pragma unroll
            for (int m = 0; m < TM; m++)
                #pragma unroll
                for (int p = 0; p < TN / 2; p++)
                    fma2(acc[m][p], av[m], bp[p]);
        }
        __syncthreads();
    }

    #pragma unroll
    for (int i = 0; i < MCH; i++) {
        #pragma unroll
        for (int mm = 0; mm < 4; mm++) {
            long long row = row0 + i * RS + trow * 4 + mm;
            int m = i * 4 + mm;
            #pragma unroll
            for (int j = 0; j < NCH; j++) {
                int col = col0 + j * CS + tcol * 4;
                float2 lo = unpack2(acc[m][j * 2]);
                float2 hi = unpack2(acc[m][j * 2 + 1]);
                float4 v = make_float4(lo.x, lo.y, hi.x, hi.y);
                if (BIAS) {
                    int cb = col % bias_mod;
                    v.x += bias[cb]; v.y += bias[cb + 1];
                    v.z += bias[cb + 2]; v.w += bias[cb + 3];
                }
                if (RELU) {
                    v.x = fmaxf(v.x, 0.f); v.y = fmaxf(v.y, 0.f);
                    v.z = fmaxf(v.z, 0.f); v.w = fmaxf(v.w, 0.f);
                }
                *(float4*)&C[row * N + col] = v;
            }
        }
    }
}

// ---------------- split-bf16 tensor-core GEMM via mma.sync ----------------
// D = (Ahi+Alo) @ (Bhi+Blo)^T  (lo*lo dropped), fp32 accumulate.
// A: [M,K] bf16 K-major; B: [N,K] bf16 K-major (z-batched via bzRows rows offset).
// Block: 256 thr, tile 128x128, BK=32. Warp grid 4x2, warp tile 32x64.
// SPLIT_OUT: write relu(D+bias) as bf16 hi/lo; else fp32 D+bias.
template <bool SPLIT_OUT>
__global__ void __launch_bounds__(256)
mma_gemm_k(const __nv_bfloat16* __restrict__ Ahi, const __nv_bfloat16* __restrict__ Alo,
           long long lda,
           const __nv_bfloat16* __restrict__ Bhi, const __nv_bfloat16* __restrict__ Blo,
           long long ldb, long long bzRows,
           const float* __restrict__ bias, int bias_mod,
           float* __restrict__ Dout,
           __nv_bfloat16* __restrict__ DhiOut, __nv_bfloat16* __restrict__ DloOut,
           long long ldd, long long dz, int K) {
    __shared__ __align__(16) __nv_bfloat16 sA[2][128][40];   // hi, lo
    __shared__ __align__(16) __nv_bfloat16 sB[2][128][40];

    const int tid = threadIdx.x, wid = tid >> 5, lane = tid & 31;
    const int wm = wid >> 1, wn = wid & 1;
    const long long z = blockIdx.z;
    const long long aRow0 = (long long)blockIdx.y * 128;
    const long long bRow0 = (long long)blockIdx.x * 128 + z * bzRows;

    const __nv_bfloat16* srcs[4] = {Ahi + aRow0 * lda, Alo + aRow0 * lda,
                                    Bhi + bRow0 * ldb, Blo + bRow0 * ldb};
    const long long lds[4] = {lda, lda, ldb, ldb};
    __nv_bfloat16* dsts[4] = {&sA[0][0][0], &sA[1][0][0], &sB[0][0][0], &sB[1][0][0]};

    float acc[2][8][4];
    #pragma unroll
    for (int mf = 0; mf < 2; mf++)
        #pragma unroll
        for (int nf = 0; nf < 8; nf++)
            #pragma unroll
            for (int q = 0; q < 4; q++) acc[mf][nf][q] = 0.0f;

    // ldmatrix per-lane offsets
    const int a_r  = lane & 15;               // row within 16
    const int a_c8 = (lane >> 4) << 3;        // k-half
    const int b_r  = lane & 7;                // n within 8
    const int b_c8 = ((lane >> 3) & 1) << 3;  // k-half (lanes 0-15 used by x2)

    for (int kc = 0; kc < K; kc += 32) {
        #pragma unroll
        for (int arr = 0; arr < 4; arr++) {
            #pragma unroll
            for (int half = 0; half < 2; half++) {
                int e = half * 256 + tid;          // 0..511
                int r = e >> 2, q = e & 3;
                *(uint4*)(dsts[arr] + r * 40 + q * 8) =
                    *(const uint4*)(srcs[arr] + (long long)r * lds[arr] + kc + q * 8);
            }
        }
        __syncthreads();

        #pragma unroll
        for (int ks = 0; ks < 2; ks++) {
            const int kk = ks * 16;
            uint32_t ahi[2][4], alo[2][4];
            #pragma unroll
            for (int mf = 0; mf < 2; mf++) {
                int row = wm * 32 + mf * 16 + a_r;
                ldm_x4(ahi[mf][0], ahi[mf][1], ahi[mf][2], ahi[mf][3],
                       smem_u32(&sA[0][row][kk + a_c8]));
                ldm_x4(alo[mf][0], alo[mf][1], alo[mf][2], alo[mf][3],
                       smem_u32(&sA[1][row][kk + a_c8]));
            }
            #pragma unroll
            for (int nf = 0; nf < 8; nf++) {
                int n = wn * 64 + nf * 8 + b_r;
                uint32_t bhi[2], blo[2];
                ldm_x2(bhi[0], bhi[1], smem_u32(&sB[0][n][kk + b_c8]));
                ldm_x2(blo[0], blo[1], smem_u32(&sB[1][n][kk + b_c8]));
                #pragma unroll
                for (int mf = 0; mf < 2; mf++) {
                    mma_bf16(acc[mf][nf], ahi[mf], bhi);
                    mma_bf16(acc[mf][nf], ahi[mf], blo);
                    mma_bf16(acc[mf][nf], alo[mf], bhi);
                }
            }
        }
        __syncthreads();
    }

    // Epilogue
    const int colBlk = blockIdx.x * 128;
    #pragma unroll
    for (int mf = 0; mf < 2; mf++) {
        #pragma unroll
        for (int nf = 0; nf < 8; nf++) {
            int col = colBlk + wn * 64 + nf * 8 + (lane & 3) * 2;
            int cb = col % bias_mod;
            float bb0 = bias[cb], bb1 = bias[cb + 1];
            long long r0 = aRow0 + wm * 32 + mf * 16 + (lane >> 2);
            #pragma unroll
            for (int h = 0; h < 2; h++) {
                long long row = r0 + h * 8;
                float v0 = acc[mf][nf][h * 2 + 0] + bb0;
                float v1 = acc[mf][nf][h * 2 + 1] + bb1;
                long long o = z * dz + row * ldd + col;
                if (SPLIT_OUT) {
                    v0 = fmaxf(v0, 0.0f); v1 = fmaxf(v1, 0.0f);
                    __nv_bfloat16 h0 = __float2bfloat16(v0);
                    __nv_bfloat16 h1 = __float2bfloat16(v1);
                    __nv_bfloat162 hv; hv.x = h0; hv.y = h1;
                    __nv_bfloat162 lv;
                    lv.x = __float2bfloat16(v0 - __bfloat162float(h0));
                    lv.y = __float2bfloat16(v1 - __bfloat162float(h1));
                    *(__nv_bfloat162*)(DhiOut + o) = hv;
                    *(__nv_bfloat162*)(DloOut + o) = lv;
                } else {
                    float2 fv; fv.x = v0; fv.y = v1;
                    *(float2*)(Dout + o) = fv;
                }
            }
        }
    }
}

// ---------------- fused persistent GRU (unchanged from R4) ----------------
__global__ void __launch_bounds__(256, 1)
gru_fused_k(const float* __restrict__ gi, const float* __restrict__ w_hh,
            const float* __restrict__ b_hh, float* __restrict__ out) {
    extern __shared__ float sm[];
    float* ws = sm;                 // 128*384
    float* hs = sm + 128 * 384;     // 64*128

    const int tid = threadIdx.x;
    const int rg = tid >> 5, cg = tid & 31;
    const int r0 = rg * 8, c0 = cg * 4;
    const long long bn0 = (long long)blockIdx.x * 64;

    for (int i = tid; i < 384 * 32; i += 256) {
        int j = i / 32, k4 = (i % 32) * 4;
        float4 v = *(const float4*)&w_hh[j * 128 + k4];
        ws[(k4 + 0) * 384 + j] = v.x; ws[(k4 + 1) * 384 + j] = v.y;
        ws[(k4 + 2) * 384 + j] = v.z; ws[(k4 + 3) * 384 + j] = v.w;
    }
    for (int i = tid; i < 64 * 128; i += 256) hs[i] = 0.0f;

    float bh_r[4], bh_z[4], bh_n[4];
    #pragma unroll
    for (int u = 0; u < 4; u++) {
        bh_r[u] = b_hh[c0 + u];
        bh_z[u] = b_hh[128 + c0 + u];
        bh_n[u] = b_hh[256 + c0 + u];
    }
    __syncthreads();

    for (int t = 0; t < T_; t++) {
        u64_t acc[8][6];
        #pragma unroll
        for (int i = 0; i < 8; i++)
            #pragma unroll
            for (int p = 0; p < 6; p++) acc[i][p] = 0ULL;

        #pragma unroll 2
        for (int k = 0; k < 128; k++) {
            u64_t av[8];
            #pragma unroll
            for (int i = 0; i < 8; i++) av[i] = bcast2(hs[(r0 + i) * 128 + k]);
            const float* wrow = &ws[k * 384];
            float4 w0 = *(const float4*)&wrow[c0];
            float4 w1 = *(const float4*)&wrow[128 + c0];
            float4 w2 = *(const float4*)&wrow[256 + c0];
            u64_t wp[6] = {lo2(w0), hi2(w0), lo2(w1), hi2(w1), lo2(w2), hi2(w2)};
            #pragma unroll
            for (int i = 0; i < 8; i++)
                #pragma unroll
                for (int p = 0; p < 6; p++)
                    fma2(acc[i][p], av[i], wp[p]);
        }
        __syncthreads();

        #pragma unroll
        for (int i = 0; i < 8; i++) {
            long long row = bn0 + r0 + i;
            const float* gp = gi + (row * T_ + t) * (3 * H_);
            float4 xr = *(const float4*)(gp + c0);
            float4 xz = *(const float4*)(gp + 128 + c0);
            float4 xn = *(const float4*)(gp + 256 + c0);
            float2 a0 = unpack2(acc[i][0]), a1 = unpack2(acc[i][1]);
            float2 a2 = unpack2(acc[i][2]), a3 = unpack2(acc[i][3]);
            float2 a4 = unpack2(acc[i][4]), a5 = unpack2(acc[i][5]);
            float hr[4] = {a0.x, a0.y, a1.x, a1.y};
            float hz[4] = {a2.x, a2.y, a3.x, a3.y};
            float hn[4] = {a4.x, a4.y, a5.x, a5.y};
            float xrv[4] = {xr.x, xr.y, xr.z, xr.w};
            float xzv[4] = {xz.x, xz.y, xz.z, xz.w};
            float xnv[4] = {xn.x, xn.y, xn.z, xn.w};
            float hv[4];
            #pragma unroll
            for (int u = 0; u < 4; u++) {
                float rr = sigmoid_fast(xrv[u] + hr[u] + bh_r[u]);
                float zz = sigmoid_fast(xzv[u] + hz[u] + bh_z[u]);
                float nn = tanh_fast(xnv[u] + rr * (hn[u] + bh_n[u]));
                float hp = hs[(r0 + i) * 128 + c0 + u];
                hv[u] = fmaf(zz, hp - nn, nn);
            }
            float4 o = make_float4(hv[0], hv[1], hv[2], hv[3]);
            *(float4*)&hs[(r0 + i) * 128 + c0] = o;
            *(float4*)&out[(row * T_ + t) * H_ + c0] = o;
        }
        __syncthreads();
    }
}

// ---------------- launch ----------------
extern "C" void kernel_launch(void* const* d_in, const int* in_sizes, int n_in,
                              void* d_out, int out_size) {
    const float* x     = (const float*)d_in[0];
    const float* adj   = (const float*)d_in[1];
    const float* gc_w0 = (const float*)d_in[2];
    const float* gc_b0 = (const float*)d_in[3];
    const float* gc_w1 = (const float*)d_in[4];
    const float* gc_b1 = (const float*)d_in[5];
    const float* w_ih  = (const float*)d_in[6];
    const float* w_hh  = (const float*)d_in[7];
    const float* b_ih  = (const float*)d_in[8];
    const float* b_hh  = (const float*)d_in[9];
    const float* w_fc  = (const float*)d_in[10];
    const float* b_fc  = (const float*)d_in[11];
    float* out = (float*)d_out;

    unsigned char* pool;
    float *adjn, *dis;
    __nv_bfloat16 *adjn_hi, *adjn_lo, *wih_hi, *wih_lo;
    cudaGetSymbolAddress((void**)&pool,    g_pool);
    cudaGetSymbolAddress((void**)&adjn,    g_adjn);
    cudaGetSymbolAddress((void**)&adjn_hi, g_adjn_hi);
    cudaGetSymbolAddress((void**)&adjn_lo, g_adjn_lo);
    cudaGetSymbolAddress((void**)&dis,     g_dis);
    cudaGetSymbolAddress((void**)&wih_hi,  g_wih_hi);
    cudaGetSymbolAddress((void**)&wih_lo,  g_wih_lo);

    // pooled regions (see layout comment at g_pool)
    __nv_bfloat16* s1t_hi = (__nv_bfloat16*)(pool + 0);
    __nv_bfloat16* s1t_lo = (__nv_bfloat16*)(pool + 201326592ULL);
    float*         h1     = (float*)(pool + 402653184ULL);
    float*         s1     = (float*)(pool + 805306368ULL);   // also Y0
    float*         gi     = (float*)(pool + 0);
    __nv_bfloat16* h2_hi  = (__nv_bfloat16*)(pool + 1207959552ULL);
    __nv_bfloat16* h2_lo  = (__nv_bfloat16*)(pool + 1409286144ULL);
    float*         gru_o  = (float*)(pool + 1207959552ULL);

    const int M = (int)M_TOT;   // 786432

    // 1) adjacency normalization (+ bf16 split) and w_ih split
    adj_rowsum_k<<<1, N_>>>(adj, dis);
    adj_norm_k<<<dim3(N_ / 256, N_), 256>>>(adj, dis, adjn, adjn_hi, adjn_lo);
    split_k<<<(3 * H_ * H_ + 255) / 256, 256>>>(w_ih, wih_hi, wih_lo, 3 * H_ * H_);

    // 2) A-hop on raw (masked) x: Y0 = adjn @ mask(x)   [per batch, N=3072]  (SIMT)
    gemm_k<128, 128, 16, 8, 8, false, true, false, false>
        <<<dim3((T_ * FIN_) / 128, N_ / 128, B_), 256>>>(
            adjn, x, nullptr, s1 /*Y0*/, N_, T_ * FIN_, N_,
            (long long)N_ * T_ * FIN_, (long long)N_ * T_ * FIN_, 1);

    // 3) h1 = relu(Y0 @ gc_w0 + b0)  (SIMT)
    gemm_k<128, 128, 16, 8, 8, false, false, true, true>
        <<<dim3(1, M / 128), 256>>>(s1 /*Y0*/, gc_w0, gc_b0, h1,
                                    M, H_, FIN_, 0, 0, H_);

    // 4) S1 = h1 @ gc_w1  (SIMT, fp32)
    gemm_k<128, 128, 16, 8, 8, false, false, false, false>
        <<<dim3(1, M / 128), 256>>>(h1, gc_w1, nullptr, s1,
                                    M, H_, H_, 0, 0, 1);

    // 4b) transpose + split: S1 -> S1T bf16 hi/lo
    transpose_split_k<<<dim3((T_ * H_) / 32, N_ / 32, B_), dim3(32, 8)>>>(s1, s1t_hi, s1t_lo);

    // 5) h2 = relu(adjn @ S1 + b1)  (mma.sync; per batch M=512, N=12288, K=512)
    mma_gemm_k<true><<<dim3((T_ * H_) / 128, N_ / 128, B_), 256>>>(
        adjn_hi, adjn_lo, N_,
        s1t_hi, s1t_lo, N_, (long long)T_ * H_,
        gc_b1, H_,
        nullptr, h2_hi, h2_lo,
        (long long)T_ * H_, (long long)N_ * T_ * H_, N_);

    // 6) GI = h2 @ w_ih^T + b_ih  (mma.sync; M=786432, N=384, K=128)
    mma_gemm_k<false><<<dim3((3 * H_) / 128, M / 128, 1), 256>>>(
        h2_hi, h2_lo, H_,
        wih_hi, wih_lo, H_, 0,
        b_ih, 3 * H_,
        gi, nullptr, nullptr,
        3 * H_, 0, H_);

    // 7) fused GRU recurrence (single persistent launch)
    constexpr int GRU_SMEM = (128 * 384 + 64 * 128) * 4;   // 229376 bytes
    cudaFuncSetAttribute(gru_fused_k, cudaFuncAttributeMaxDynamicSharedMemorySize, GRU_SMEM);
    gru_fused_k<<<BN_TOT / 64, 256, GRU_SMEM>>>(gi, w_hh, b_hh, gru_o);

    // 8) FC: out = gru_out @ w_fc + b_fc  (SIMT)
    gemm_k<128, 32, 16, 8, 4, false, false, false, true>
        <<<dim3(1, M / 128), 128>>>(gru_o, w_fc, b_fc, out,
                                    M, FOUT_, H_, 0, 0, FOUT_);
}

// round 10
// speedup vs baseline: 3.5922x; 1.0745x over previous
#include <cuda_runtime.h>
#include <cuda_bf16.h>
#include <cstdint>
#include <math.h>

#define B_    16
#define N_    512
#define T_    96
#define FIN_  32
#define H_    128
#define FOUT_ 32

constexpr int       BN_TOT = B_ * N_;                       // 8192
constexpr long long M_TOT  = (long long)B_ * N_ * T_;       // 786432

using u64_t = unsigned long long;

// ---------------- pooled scratch (host .bss shadow must stay < 2 GiB) ----------------
//   [0, 201326592)            s1t_hi   (steps 4b..5)     } overlapped by gi (step 6..7)
//   [201326592, 402653184)    s1t_lo   (steps 4b..5)     }
//   [402653184, 805306368)    h1 fp32  (steps 3..4)      }
//   [805306368, 1207959552)   Y0/S1 fp32 (steps 2..4b)   }
//   [0, 1207959552)           gi fp32  (steps 6..7)
//   [1207959552, 1409286144)  h2_hi    (steps 5..6)      } overlapped by gru_out (7..8)
//   [1409286144, 1610612736)  h2_lo    (steps 5..6)      }
//   [1207959552, 1610612736)  gru_out fp32 (steps 7..8)
constexpr size_t POOL_BYTES = 1610612736ULL;   // 1.5 GiB
__device__ __align__(128) unsigned char g_pool[POOL_BYTES];

__device__ float g_adjn[N_ * N_];
__device__ __nv_bfloat16 g_adjn_hi[N_ * N_];
__device__ __nv_bfloat16 g_adjn_lo[N_ * N_];
__device__ float g_dis[N_];
__device__ __nv_bfloat16 g_wih_hi[3 * H_ * H_];
__device__ __nv_bfloat16 g_wih_lo[3 * H_ * H_];

// ---------------- f32x2 helpers ----------------
__device__ __forceinline__ u64_t bcast2(float x) {
    u64_t r; asm("mov.b64 %0, {%1,%2};" : "=l"(r) : "f"(x), "f"(x)); return r;
}
__device__ __forceinline__ u64_t lo2(const float4& v) {
    u64_t r; asm("mov.b64 %0, {%1,%2};" : "=l"(r) : "f"(v.x), "f"(v.y)); return r;
}
__device__ __forceinline__ u64_t hi2(const float4& v) {
    u64_t r; asm("mov.b64 %0, {%1,%2};" : "=l"(r) : "f"(v.z), "f"(v.w)); return r;
}
__device__ __forceinline__ void fma2(u64_t& d, u64_t a, u64_t b) {
    asm("fma.rn.f32x2 %0, %1, %2, %0;" : "+l"(d) : "l"(a), "l"(b));
}
__device__ __forceinline__ float2 unpack2(u64_t v) {
    float2 r; asm("mov.b64 {%0,%1}, %2;" : "=f"(r.x), "=f"(r.y) : "l"(v)); return r;
}

// ---------------- FMA-only activations (no MUFU) ----------------
__device__ __forceinline__ float frcp_fast(float d) {
    float r = __uint_as_float(0x7EF311C3u - __float_as_uint(d));
    r = r * (2.0f - d * r);
    r = r * (2.0f - d * r);
    return r;
}
__device__ __forceinline__ float tanh_fast(float x) {
    x = fminf(7.90531f, fmaxf(-7.90531f, x));
    float x2 = x * x;
    float p = -2.76076847742355e-16f;
    p = fmaf(p, x2, 2.00018790482477e-13f);
    p = fmaf(p, x2, -8.60467152213735e-11f);
    p = fmaf(p, x2, 5.12229709037114e-08f);
    p = fmaf(p, x2, 1.48572235717979e-05f);
    p = fmaf(p, x2, 6.37261928875436e-04f);
    p = fmaf(p, x2, 4.89352455891786e-03f);
    p = p * x;
    float q = 1.19825839466702e-06f;
    q = fmaf(q, x2, 1.18534705686654e-04f);
    q = fmaf(q, x2, 2.26843463243900e-03f);
    q = fmaf(q, x2, 4.89352518554385e-03f);
    return p * frcp_fast(q);
}
__device__ __forceinline__ float sigmoid_fast(float x) {
    return 0.5f + 0.5f * tanh_fast(0.5f * x);
}

// ---------------- mma.sync helpers (sm_80+ path, works on plain sm_100) ----------------
__device__ __forceinline__ uint32_t smem_u32(const void* p) {
    uint32_t a;
    asm("{ .reg .u64 t; cvta.to.shared.u64 t, %1; cvt.u32.u64 %0, t; }" : "=r"(a) : "l"(p));
    return a;
}
__device__ __forceinline__ void ldm_x4(uint32_t& r0, uint32_t& r1, uint32_t& r2, uint32_t& r3,
                                       uint32_t addr) {
    asm volatile("ldmatrix.sync.aligned.m8n8.x4.shared.b16 {%0,%1,%2,%3}, [%4];"
                 : "=r"(r0), "=r"(r1), "=r"(r2), "=r"(r3) : "r"(addr));
}
__device__ __forceinline__ void ldm_x2(uint32_t& r0, uint32_t& r1, uint32_t addr) {
    asm volatile("ldmatrix.sync.aligned.m8n8.x2.shared.b16 {%0,%1}, [%2];"
                 : "=r"(r0), "=r"(r1) : "r"(addr));
}
__device__ __forceinline__ void mma_bf16(float* c, const uint32_t* a, const uint32_t* b) {
    asm volatile("mma.sync.aligned.m16n8k16.row.col.f32.bf16.bf16.f32 "
                 "{%0,%1,%2,%3}, {%4,%5,%6,%7}, {%8,%9}, {%0,%1,%2,%3};"
                 : "+f"(c[0]), "+f"(c[1]), "+f"(c[2]), "+f"(c[3])
                 : "r"(a[0]), "r"(a[1]), "r"(a[2]), "r"(a[3]), "r"(b[0]), "r"(b[1]));
}
__device__ __forceinline__ void cp16(uint32_t dst, const void* src) {
    asm volatile("cp.async.ca.shared.global [%0], [%1], 16;" :: "r"(dst), "l"(src));
}
__device__ __forceinline__ void cp_commit() {
    asm volatile("cp.async.commit_group;" ::: "memory");
}
template <int NW>
__device__ __forceinline__ void cp_wait() {
    asm volatile("cp.async.wait_group %0;" :: "n"(NW) : "memory");
}

// ---------------- adjacency normalization ----------------
__global__ void adj_rowsum_k(const float* __restrict__ adj, float* __restrict__ dis) {
    int i = threadIdx.x;
    float s = 1.0f;
    for (int j = 0; j < N_; j++) s += adj[i * N_ + j];
    dis[i] = (s > 0.0f) ? rsqrtf(s) : 0.0f;
}
__global__ void adj_norm_k(const float* __restrict__ adj, const float* __restrict__ dis,
                           float* __restrict__ out,
                           __nv_bfloat16* __restrict__ ohi, __nv_bfloat16* __restrict__ olo) {
    int j = blockIdx.x * blockDim.x + threadIdx.x;
    int i = blockIdx.y;
    float a = adj[i * N_ + j] + (i == j ? 1.0f : 0.0f);
    float v = dis[i] * a * dis[j];
    out[i * N_ + j] = v;
    __nv_bfloat16 h = __float2bfloat16(v);
    ohi[i * N_ + j] = h;
    olo[i * N_ + j] = __float2bfloat16(v - __bfloat162float(h));
}

// ---------------- elementwise fp32 -> bf16 hi/lo split ----------------
__global__ void split_k(const float* __restrict__ src, __nv_bfloat16* __restrict__ hi,
                        __nv_bfloat16* __restrict__ lo, int n) {
    int i = blockIdx.x * blockDim.x + threadIdx.x;
    if (i >= n) return;
    float v = src[i];
    __nv_bfloat16 h = __float2bfloat16(v);
    hi[i] = h;
    lo[i] = __float2bfloat16(v - __bfloat162float(h));
}

// ---------------- transpose + split: S1[b][node][c] -> S1T[b][c][node] bf16 hi/lo ----------------
__global__ void transpose_split_k(const float* __restrict__ src,
                                  __nv_bfloat16* __restrict__ hi, __nv_bfloat16* __restrict__ lo) {
    __shared__ float tile[32][33];
    const int b = blockIdx.z;
    const long long cBase = (long long)blockIdx.x * 32;   // c in [0,12288)
    const long long nBase = (long long)blockIdx.y * 32;   // node in [0,512)
    const float* s = src + (long long)b * N_ * (T_ * H_);
    #pragma unroll
    for (int i = threadIdx.y; i < 32; i += 8)
        tile[i][threadIdx.x] = s[(nBase + i) * (T_ * H_) + cBase + threadIdx.x];
    __syncthreads();
    const long long ob = (long long)b * (T_ * H_) * N_;
    #pragma unroll
    for (int i = threadIdx.y; i < 32; i += 8) {
        float v = tile[threadIdx.x][i];                    // [node=nBase+tx][c=cBase+i]
        __nv_bfloat16 h = __float2bfloat16(v);
        long long o = ob + (cBase + i) * N_ + nBase + threadIdx.x;
        hi[o] = h;
        lo[o] = __float2bfloat16(v - __bfloat162float(h));
    }
}

// ---------------- tiled fp32 GEMM with FFMA2 (SIMT; steps 2,3,4, FC) ----------------
template <int BM, int BN, int BK, int TM, int TN, bool TRANSB, bool MASKB, bool RELU, bool BIAS>
__global__ void __launch_bounds__((BM / TM) * (BN / TN))
gemm_k(const float* __restrict__ A, const float* __restrict__ B,
       const float* __restrict__ bias, float* __restrict__ C,
       int M, int N, int K, long long sB, long long sC, int bias_mod) {
    constexpr int THREADS = (BM / TM) * (BN / TN);
    constexpr int MCH = TM / 4, NCH = TN / 4;
    constexpr int RS = BM / MCH, CS = BN / NCH;

    B += (long long)blockIdx.z * sB;
    C += (long long)blockIdx.z * sC;

    __shared__ float As[BK][BM + 4];
    __shared__ float Bs[BK][BN + 4];

    const int tid   = threadIdx.x;
    const int tcols = BN / TN;
    const int trow  = tid / tcols;
    const int tcol  = tid % tcols;
    const long long row0 = (long long)blockIdx.y * BM;
    const int col0 = blockIdx.x * BN;

    u64_t acc[TM][TN / 2];
    #pragma unroll
    for (int m = 0; m < TM; m++)
        #pragma unroll
        for (int p = 0; p < TN / 2; p++) acc[m][p] = 0ULL;

    for (int k0 = 0; k0 < K; k0 += BK) {
        #pragma unroll
        for (int i = tid; i < BM * BK / 4; i += THREADS) {
            int r = i / (BK / 4), kk = (i % (BK / 4)) * 4;
            float4 v = *(const float4*)&A[(row0 + r) * K + k0 + kk];
            As[kk + 0][r] = v.x; As[kk + 1][r] = v.y;
            As[kk + 2][r] = v.z; As[kk + 3][r] = v.w;
        }
        if (!TRANSB) {
            #pragma unroll
            for (int i = tid; i < BK * BN / 4; i += THREADS) {
                int r = i / (BN / 4), c = (i % (BN / 4)) * 4;
                float4 v = *(const float4*)&B[(long long)(k0 + r) * N + col0 + c];
                if (MASKB) {
                    if (v.x == -1.0f) v.x = 0.0f;
                    if (v.y == -1.0f) v.y = 0.0f;
                    if (v.z == -1.0f) v.z = 0.0f;
                    if (v.w == -1.0f) v.w = 0.0f;
                }
                *(float4*)&Bs[r][c] = v;
            }
        } else {
            #pragma unroll
            for (int i = tid; i < BN * BK / 4; i += THREADS) {
                int c = i / (BK / 4), kk = (i % (BK / 4)) * 4;
                float4 v = *(const float4*)&B[(long long)(col0 + c) * K + k0 + kk];
                Bs[kk + 0][c] = v.x; Bs[kk + 1][c] = v.y;
                Bs[kk + 2][c] = v.z; Bs[kk + 3][c] = v.w;
            }
        }
        __syncthreads();

        #pragma unroll 4
        for (int k = 0; k < BK; k++) {
            u64_t av[TM];
            #pragma unroll
            for (int i = 0; i < MCH; i++) {
                float4 a = *(const float4*)&As[k][i * RS + trow * 4];
                av[i * 4 + 0] = bcast2(a.x); av[i * 4 + 1] = bcast2(a.y);
                av[i * 4 + 2] = bcast2(a.z); av[i * 4 + 3] = bcast2(a.w);
            }
            u64_t bp[TN / 2];
            #pragma unroll
            for (int j = 0; j < NCH; j++) {
                float4 b = *(const float4*)&Bs[k][j * CS + tcol * 4];
                bp[j * 2 + 0] = lo2(b);
                bp[j * 2 + 1] = hi2(b);
            }
            #pragma unroll
            for (int m = 0; m < TM; m++)
                #pragma unroll
                for (int p = 0; p < TN / 2; p++)
                    fma2(acc[m][p], av[m], bp[p]);
        }
        __syncthreads();
    }

    #pragma unroll
    for (int i = 0; i < MCH; i++) {
        #pragma unroll
        for (int mm = 0; mm < 4; mm++) {
            long long row = row0 + i * RS + trow * 4 + mm;
            int m = i * 4 + mm;
            #pragma unroll
            for (int j = 0; j < NCH; j++) {
                int col = col0 + j * CS + tcol * 4;
                float2 lo = unpack2(acc[m][j * 2]);
                float2 hi = unpack2(acc[m][j * 2 + 1]);
                float4 v = make_float4(lo.x, lo.y, hi.x, hi.y);
                if (BIAS) {
                    int cb = col % bias_mod;
                    v.x += bias[cb]; v.y += bias[cb + 1];
                    v.z += bias[cb + 2]; v.w += bias[cb + 3];
                }
                if (RELU) {
                    v.x = fmaxf(v.x, 0.f); v.y = fmaxf(v.y, 0.f);
                    v.z = fmaxf(v.z, 0.f); v.w = fmaxf(v.w, 0.f);
                }
                *(float4*)&C[row * N + col] = v;
            }
        }
    }
}

// ---------------- split-bf16 tensor-core GEMM via mma.sync + cp.async 2-stage ----------------
// D = (Ahi+Alo) @ (Bhi+Blo)^T  (lo*lo dropped), fp32 accumulate.
// A: [M,K] bf16 K-major; B: [N,K] bf16 K-major (z-batched via bzRows rows offset).
// Block: 256 thr, tile 128x128, BK=32. Warp grid 4x2, warp tile 32x64.
// Dynamic smem: 2 stages x 4 arrays x 128 rows x 40 bf16 = 81920 bytes.
constexpr int MMA_ARR  = 128 * 40;                 // bf16 elems per array
constexpr int MMA_STAGE = 4 * MMA_ARR;             // per stage
constexpr int MMA_SMEM = 2 * MMA_STAGE * 2;        // bytes = 81920

template <bool SPLIT_OUT>
__global__ void __launch_bounds__(256)
mma_gemm_k(const __nv_bfloat16* __restrict__ Ahi, const __nv_bfloat16* __restrict__ Alo,
           long long lda,
           const __nv_bfloat16* __restrict__ Bhi, const __nv_bfloat16* __restrict__ Blo,
           long long ldb, long long bzRows,
           const float* __restrict__ bias, int bias_mod,
           float* __restrict__ Dout,
           __nv_bfloat16* __restrict__ DhiOut, __nv_bfloat16* __restrict__ DloOut,
           long long ldd, long long dz, int K) {
    extern __shared__ __align__(16) __nv_bfloat16 smem[];

    const int tid = threadIdx.x, wid = tid >> 5, lane = tid & 31;
    const int wm = wid >> 1, wn = wid & 1;
    const long long z = blockIdx.z;
    const long long aRow0 = (long long)blockIdx.y * 128;
    const long long bRow0 = (long long)blockIdx.x * 128 + z * bzRows;

    const __nv_bfloat16* srcs[4] = {Ahi + aRow0 * lda, Alo + aRow0 * lda,
                                    Bhi + bRow0 * ldb, Blo + bRow0 * ldb};
    const long long lds[4] = {lda, lda, ldb, ldb};

    // per-thread cp.async targets: 2 chunks per array (512 16B-chunks, 256 thr)
    // chunk e: row r=e>>2, 16B-quad q=e&3
    const int e0 = tid, e1 = tid + 256;
    const int r0c = e0 >> 2, q0c = e0 & 3;
    const int r1c = e1 >> 2, q1c = e1 & 3;

    auto load_stage = [&](int stage, int kc) {
        #pragma unroll
        for (int arr = 0; arr < 4; arr++) {
            __nv_bfloat16* dst = smem + stage * MMA_STAGE + arr * MMA_ARR;
            cp16(smem_u32(dst + r0c * 40 + q0c * 8),
                 srcs[arr] + (long long)r0c * lds[arr] + kc + q0c * 8);
            cp16(smem_u32(dst + r1c * 40 + q1c * 8),
                 srcs[arr] + (long long)r1c * lds[arr] + kc + q1c * 8);
        }
        cp_commit();
    };

    float acc[2][8][4];
    #pragma unroll
    for (int mf = 0; mf < 2; mf++)
        #pragma unroll
        for (int nf = 0; nf < 8; nf++)
            #pragma unroll
            for (int q = 0; q < 4; q++) acc[mf][nf][q] = 0.0f;

    // ldmatrix per-lane offsets
    const int a_r  = lane & 15;
    const int a_c8 = (lane >> 4) << 3;
    const int b_r  = lane & 7;
    const int b_c8 = ((lane >> 3) & 1) << 3;

    const int nk = K >> 5;              // K/32 chunks
    load_stage(0, 0);

    for (int i = 0; i < nk; i++) {
        const int stage = i & 1;
        if (i + 1 < nk) {
            load_stage(stage ^ 1, (i + 1) << 5);
            cp_wait<1>();
        } else {
            cp_wait<0>();
        }
        __syncthreads();

        const __nv_bfloat16* sAhi = smem + stage * MMA_STAGE + 0 * MMA_ARR;
        const __nv_bfloat16* sAlo = smem + stage * MMA_STAGE + 1 * MMA_ARR;
        const __nv_bfloat16* sBhi = smem + stage * MMA_STAGE + 2 * MMA_ARR;
        const __nv_bfloat16* sBlo = smem + stage * MMA_STAGE + 3 * MMA_ARR;

        #pragma unroll
        for (int ks = 0; ks < 2; ks++) {
            const int kk = ks * 16;
            uint32_t ahi[2][4], alo[2][4];
            #pragma unroll
            for (int mf = 0; mf < 2; mf++) {
                int row = wm * 32 + mf * 16 + a_r;
                ldm_x4(ahi[mf][0], ahi[mf][1], ahi[mf][2], ahi[mf][3],
                       smem_u32(sAhi + row * 40 + kk + a_c8));
                ldm_x4(alo[mf][0], alo[mf][1], alo[mf][2], alo[mf][3],
                       smem_u32(sAlo + row * 40 + kk + a_c8));
            }
            #pragma unroll
            for (int nf = 0; nf < 8; nf++) {
                int n = wn * 64 + nf * 8 + b_r;
                uint32_t bhi[2], blo[2];
                ldm_x2(bhi[0], bhi[1], smem_u32(sBhi + n * 40 + kk + b_c8));
                ldm_x2(blo[0], blo[1], smem_u32(sBlo + n * 40 + kk + b_c8));
                #pragma unroll
                for (int mf = 0; mf < 2; mf++) {
                    mma_bf16(acc[mf][nf], ahi[mf], bhi);
                    mma_bf16(acc[mf][nf], ahi[mf], blo);
                    mma_bf16(acc[mf][nf], alo[mf], bhi);
                }
            }
        }
        __syncthreads();   // protect stage^1 (written next iter) from in-flight readers
    }

    // Epilogue
    const int colBlk = blockIdx.x * 128;
    #pragma unroll
    for (int mf = 0; mf < 2; mf++) {
        #pragma unroll
        for (int nf = 0; nf < 8; nf++) {
            int col = colBlk + wn * 64 + nf * 8 + (lane & 3) * 2;
            int cb = col % bias_mod;
            float bb0 = bias[cb], bb1 = bias[cb + 1];
            long long r0 = aRow0 + wm * 32 + mf * 16 + (lane >> 2);
            #pragma unroll
            for (int h = 0; h < 2; h++) {
                long long row = r0 + h * 8;
                float v0 = acc[mf][nf][h * 2 + 0] + bb0;
                float v1 = acc[mf][nf][h * 2 + 1] + bb1;
                long long o = z * dz + row * ldd + col;
                if (SPLIT_OUT) {
                    v0 = fmaxf(v0, 0.0f); v1 = fmaxf(v1, 0.0f);
                    __nv_bfloat16 h0 = __float2bfloat16(v0);
                    __nv_bfloat16 h1 = __float2bfloat16(v1);
                    __nv_bfloat162 hv; hv.x = h0; hv.y = h1;
                    __nv_bfloat162 lv;
                    lv.x = __float2bfloat16(v0 - __bfloat162float(h0));
                    lv.y = __float2bfloat16(v1 - __bfloat162float(h1));
                    *(__nv_bfloat162*)(DhiOut + o) = hv;
                    *(__nv_bfloat162*)(DloOut + o) = lv;
                } else {
                    float2 fv; fv.x = v0; fv.y = v1;
                    *(float2*)(Dout + o) = fv;
                }
            }
        }
    }
}

// ---------------- fused persistent GRU (unchanged) ----------------
__global__ void __launch_bounds__(256, 1)
gru_fused_k(const float* __restrict__ gi, const float* __restrict__ w_hh,
            const float* __restrict__ b_hh, float* __restrict__ out) {
    extern __shared__ float sm[];
    float* ws = sm;                 // 128*384
    float* hs = sm + 128 * 384;     // 64*128

    const int tid = threadIdx.x;
    const int rg = tid >> 5, cg = tid & 31;
    const int r0 = rg * 8, c0 = cg * 4;
    const long long bn0 = (long long)blockIdx.x * 64;

    for (int i = tid; i < 384 * 32; i += 256) {
        int j = i / 32, k4 = (i % 32) * 4;
        float4 v = *(const float4*)&w_hh[j * 128 + k4];
        ws[(k4 + 0) * 384 + j] = v.x; ws[(k4 + 1) * 384 + j] = v.y;
        ws[(k4 + 2) * 384 + j] = v.z; ws[(k4 + 3) * 384 + j] = v.w;
    }
    for (int i = tid; i < 64 * 128; i += 256) hs[i] = 0.0f;

    float bh_r[4], bh_z[4], bh_n[4];
    #pragma unroll
    for (int u = 0; u < 4; u++) {
        bh_r[u] = b_hh[c0 + u];
        bh_z[u] = b_hh[128 + c0 + u];
        bh_n[u] = b_hh[256 + c0 + u];
    }
    __syncthreads();

    for (int t = 0; t < T_; t++) {
        u64_t acc[8][6];
        #pragma unroll
        for (int i = 0; i < 8; i++)
            #pragma unroll
            for (int p = 0; p < 6; p++) acc[i][p] = 0ULL;

        #pragma unroll 2
        for (int k = 0; k < 128; k++) {
            u64_t av[8];
            #pragma unroll
            for (int i = 0; i < 8; i++) av[i] = bcast2(hs[(r0 + i) * 128 + k]);
            const float* wrow = &ws[k * 384];
            float4 w0 = *(const float4*)&wrow[c0];
            float4 w1 = *(const float4*)&wrow[128 + c0];
            float4 w2 = *(const float4*)&wrow[256 + c0];
            u64_t wp[6] = {lo2(w0), hi2(w0), lo2(w1), hi2(w1), lo2(w2), hi2(w2)};
            #pragma unroll
            for (int i = 0; i < 8; i++)
                #pragma unroll
                for (int p = 0; p < 6; p++)
                    fma2(acc[i][p], av[i], wp[p]);
        }
        __syncthreads();

        #pragma unroll
        for (int i = 0; i < 8; i++) {
            long long row = bn0 + r0 + i;
            const float* gp = gi + (row * T_ + t) * (3 * H_);
            float4 xr = *(const float4*)(gp + c0);
            float4 xz = *(const float4*)(gp + 128 + c0);
            float4 xn = *(const float4*)(gp + 256 + c0);
            float2 a0 = unpack2(acc[i][0]), a1 = unpack2(acc[i][1]);
            float2 a2 = unpack2(acc[i][2]), a3 = unpack2(acc[i][3]);
            float2 a4 = unpack2(acc[i][4]), a5 = unpack2(acc[i][5]);
            float hr[4] = {a0.x, a0.y, a1.x, a1.y};
            float hz[4] = {a2.x, a2.y, a3.x, a3.y};
            float hn[4] = {a4.x, a4.y, a5.x, a5.y};
            float xrv[4] = {xr.x, xr.y, xr.z, xr.w};
            float xzv[4] = {xz.x, xz.y, xz.z, xz.w};
            float xnv[4] = {xn.x, xn.y, xn.z, xn.w};
            float hv[4];
            #pragma unroll
            for (int u = 0; u < 4; u++) {
                float rr = sigmoid_fast(xrv[u] + hr[u] + bh_r[u]);
                float zz = sigmoid_fast(xzv[u] + hz[u] + bh_z[u]);
                float nn = tanh_fast(xnv[u] + rr * (hn[u] + bh_n[u]));
                float hp = hs[(r0 + i) * 128 + c0 + u];
                hv[u] = fmaf(zz, hp - nn, nn);
            }
            float4 o = make_float4(hv[0], hv[1], hv[2], hv[3]);
            *(float4*)&hs[(r0 + i) * 128 + c0] = o;
            *(float4*)&out[(row * T_ + t) * H_ + c0] = o;
        }
        __syncthreads();
    }
}

// ---------------- launch ----------------
extern "C" void kernel_launch(void* const* d_in, const int* in_sizes, int n_in,
                              void* d_out, int out_size) {
    const float* x     = (const float*)d_in[0];
    const float* adj   = (const float*)d_in[1];
    const float* gc_w0 = (const float*)d_in[2];
    const float* gc_b0 = (const float*)d_in[3];
    const float* gc_w1 = (const float*)d_in[4];
    const float* gc_b1 = (const float*)d_in[5];
    const float* w_ih  = (const float*)d_in[6];
    const float* w_hh  = (const float*)d_in[7];
    const float* b_ih  = (const float*)d_in[8];
    const float* b_hh  = (const float*)d_in[9];
    const float* w_fc  = (const float*)d_in[10];
    const float* b_fc  = (const float*)d_in[11];
    float* out = (float*)d_out;

    unsigned char* pool;
    float *adjn, *dis;
    __nv_bfloat16 *adjn_hi, *adjn_lo, *wih_hi, *wih_lo;
    cudaGetSymbolAddress((void**)&pool,    g_pool);
    cudaGetSymbolAddress((void**)&adjn,    g_adjn);
    cudaGetSymbolAddress((void**)&adjn_hi, g_adjn_hi);
    cudaGetSymbolAddress((void**)&adjn_lo, g_adjn_lo);
    cudaGetSymbolAddress((void**)&dis,     g_dis);
    cudaGetSymbolAddress((void**)&wih_hi,  g_wih_hi);
    cudaGetSymbolAddress((void**)&wih_lo,  g_wih_lo);

    __nv_bfloat16* s1t_hi = (__nv_bfloat16*)(pool + 0);
    __nv_bfloat16* s1t_lo = (__nv_bfloat16*)(pool + 201326592ULL);
    float*         h1     = (float*)(pool + 402653184ULL);
    float*         s1     = (float*)(pool + 805306368ULL);   // also Y0
    float*         gi     = (float*)(pool + 0);
    __nv_bfloat16* h2_hi  = (__nv_bfloat16*)(pool + 1207959552ULL);
    __nv_bfloat16* h2_lo  = (__nv_bfloat16*)(pool + 1409286144ULL);
    float*         gru_o  = (float*)(pool + 1207959552ULL);

    const int M = (int)M_TOT;   // 786432

    // 1) adjacency normalization (+ bf16 split) and w_ih split
    adj_rowsum_k<<<1, N_>>>(adj, dis);
    adj_norm_k<<<dim3(N_ / 256, N_), 256>>>(adj, dis, adjn, adjn_hi, adjn_lo);
    split_k<<<(3 * H_ * H_ + 255) / 256, 256>>>(w_ih, wih_hi, wih_lo, 3 * H_ * H_);

    // 2) A-hop on raw (masked) x: Y0 = adjn @ mask(x)   (SIMT)
    gemm_k<128, 128, 16, 8, 8, false, true, false, false>
        <<<dim3((T_ * FIN_) / 128, N_ / 128, B_), 256>>>(
            adjn, x, nullptr, s1 /*Y0*/, N_, T_ * FIN_, N_,
            (long long)N_ * T_ * FIN_, (long long)N_ * T_ * FIN_, 1);

    // 3) h1 = relu(Y0 @ gc_w0 + b0)  (SIMT)
    gemm_k<128, 128, 16, 8, 8, false, false, true, true>
        <<<dim3(1, M / 128), 256>>>(s1 /*Y0*/, gc_w0, gc_b0, h1,
                                    M, H_, FIN_, 0, 0, H_);

    // 4) S1 = h1 @ gc_w1  (SIMT, fp32)
    gemm_k<128, 128, 16, 8, 8, false, false, false, false>
        <<<dim3(1, M / 128), 256>>>(h1, gc_w1, nullptr, s1,
                                    M, H_, H_, 0, 0, 1);

    // 4b) transpose + split: S1 -> S1T bf16 hi/lo
    transpose_split_k<<<dim3((T_ * H_) / 32, N_ / 32, B_), dim3(32, 8)>>>(s1, s1t_hi, s1t_lo);

    // 5) h2 = relu(adjn @ S1 + b1)  (mma.sync + cp.async; per batch M=512, N=12288, K=512)
    cudaFuncSetAttribute(mma_gemm_k<true>,  cudaFuncAttributeMaxDynamicSharedMemorySize, MMA_SMEM);
    cudaFuncSetAttribute(mma_gemm_k<false>, cudaFuncAttributeMaxDynamicSharedMemorySize, MMA_SMEM);
    mma_gemm_k<true><<<dim3((T_ * H_) / 128, N_ / 128, B_), 256, MMA_SMEM>>>(
        adjn_hi, adjn_lo, N_,
        s1t_hi, s1t_lo, N_, (long long)T_ * H_,
        gc_b1, H_,
        nullptr, h2_hi, h2_lo,
        (long long)T_ * H_, (long long)N_ * T_ * H_, N_);

    // 6) GI = h2 @ w_ih^T + b_ih  (mma.sync + cp.async; M=786432, N=384, K=128)
    mma_gemm_k<false><<<dim3((3 * H_) / 128, M / 128, 1), 256, MMA_SMEM>>>(
        h2_hi, h2_lo, H_,
        wih_hi, wih_lo, H_, 0,
        b_ih, 3 * H_,
        gi, nullptr, nullptr,
        3 * H_, 0, H_);

    // 7) fused GRU recurrence (single persistent launch)
    constexpr int GRU_SMEM = (128 * 384 + 64 * 128) * 4;   // 229376 bytes
    cudaFuncSetAttribute(gru_fused_k, cudaFuncAttributeMaxDynamicSharedMemorySize, GRU_SMEM);
    gru_fused_k<<<BN_TOT / 64, 256, GRU_SMEM>>>(gi, w_hh, b_hh, gru_o);

    // 8) FC: out = gru_out @ w_fc + b_fc  (SIMT)
    gemm_k<128, 32, 16, 8, 4, false, false, false, true>
        <<<dim3(1, M / 128), 128>>>(gru_o, w_fc, b_fc, out,
                                    M, FOUT_, H_, 0, 0, FOUT_);
}

// round 13
// speedup vs baseline: 4.2754x; 1.1902x over previous
#include <cuda_runtime.h>
#include <cuda_bf16.h>
#include <cstdint>
#include <math.h>

#define B_    16
#define N_    512
#define T_    96
#define FIN_  32
#define H_    128
#define FOUT_ 32

constexpr int       BN_TOT = B_ * N_;                       // 8192
constexpr long long M_TOT  = (long long)B_ * N_ * T_;       // 786432

using u64_t = unsigned long long;

// ---------------- pooled scratch (host .bss shadow must stay < 2 GiB) ----------------
constexpr size_t POOL_BYTES = 1610612736ULL;   // 1.5 GiB
__device__ __align__(128) unsigned char g_pool[POOL_BYTES];

__device__ float g_adjn[N_ * N_];
__device__ __nv_bfloat16 g_adjn_hi[N_ * N_];
__device__ __nv_bfloat16 g_adjn_lo[N_ * N_];
__device__ float g_dis[N_];
__device__ __nv_bfloat16 g_wih_hi[3 * H_ * H_];
__device__ __nv_bfloat16 g_wih_lo[3 * H_ * H_];

// ---------------- f32x2 helpers ----------------
__device__ __forceinline__ u64_t bcast2(float x) {
    u64_t r; asm("mov.b64 %0, {%1,%2};" : "=l"(r) : "f"(x), "f"(x)); return r;
}
__device__ __forceinline__ u64_t lo2(const float4& v) {
    u64_t r; asm("mov.b64 %0, {%1,%2};" : "=l"(r) : "f"(v.x), "f"(v.y)); return r;
}
__device__ __forceinline__ u64_t hi2(const float4& v) {
    u64_t r; asm("mov.b64 %0, {%1,%2};" : "=l"(r) : "f"(v.z), "f"(v.w)); return r;
}
__device__ __forceinline__ void fma2(u64_t& d, u64_t a, u64_t b) {
    asm("fma.rn.f32x2 %0, %1, %2, %0;" : "+l"(d) : "l"(a), "l"(b));
}
__device__ __forceinline__ float2 unpack2(u64_t v) {
    float2 r; asm("mov.b64 {%0,%1}, %2;" : "=f"(r.x), "=f"(r.y) : "l"(v)); return r;
}

// ---------------- FMA-only activations (no MUFU) ----------------
__device__ __forceinline__ float frcp_fast(float d) {
    float r = __uint_as_float(0x7EF311C3u - __float_as_uint(d));
    r = r * (2.0f - d * r);
    r = r * (2.0f - d * r);
    return r;
}
__device__ __forceinline__ float tanh_fast(float x) {
    x = fminf(7.90531f, fmaxf(-7.90531f, x));
    float x2 = x * x;
    float p = -2.76076847742355e-16f;
    p = fmaf(p, x2, 2.00018790482477e-13f);
    p = fmaf(p, x2, -8.60467152213735e-11f);
    p = fmaf(p, x2, 5.12229709037114e-08f);
    p = fmaf(p, x2, 1.48572235717979e-05f);
    p = fmaf(p, x2, 6.37261928875436e-04f);
    p = fmaf(p, x2, 4.89352455891786e-03f);
    p = p * x;
    float q = 1.19825839466702e-06f;
    q = fmaf(q, x2, 1.18534705686654e-04f);
    q = fmaf(q, x2, 2.26843463243900e-03f);
    q = fmaf(q, x2, 4.89352518554385e-03f);
    return p * frcp_fast(q);
}
__device__ __forceinline__ float sigmoid_fast(float x) {
    return 0.5f + 0.5f * tanh_fast(0.5f * x);
}

// ---------------- mma.sync helpers (sm_80+ path, works on plain sm_100) ----------------
__device__ __forceinline__ uint32_t smem_u32(const void* p) {
    uint32_t a;
    asm("{ .reg .u64 t; cvta.to.shared.u64 t, %1; cvt.u32.u64 %0, t; }" : "=r"(a) : "l"(p));
    return a;
}
__device__ __forceinline__ void ldm_x4(uint32_t& r0, uint32_t& r1, uint32_t& r2, uint32_t& r3,
                                       uint32_t addr) {
    asm volatile("ldmatrix.sync.aligned.m8n8.x4.shared.b16 {%0,%1,%2,%3}, [%4];"
                 : "=r"(r0), "=r"(r1), "=r"(r2), "=r"(r3) : "r"(addr));
}
__device__ __forceinline__ void ldm_x2(uint32_t& r0, uint32_t& r1, uint32_t addr) {
    asm volatile("ldmatrix.sync.aligned.m8n8.x2.shared.b16 {%0,%1}, [%2];"
                 : "=r"(r0), "=r"(r1) : "r"(addr));
}
__device__ __forceinline__ void mma_bf16(float* c, const uint32_t* a, const uint32_t* b) {
    asm volatile("mma.sync.aligned.m16n8k16.row.col.f32.bf16.bf16.f32 "
                 "{%0,%1,%2,%3}, {%4,%5,%6,%7}, {%8,%9}, {%0,%1,%2,%3};"
                 : "+f"(c[0]), "+f"(c[1]), "+f"(c[2]), "+f"(c[3])
                 : "r"(a[0]), "r"(a[1]), "r"(a[2]), "r"(a[3]), "r"(b[0]), "r"(b[1]));
}
__device__ __forceinline__ void cp16(uint32_t dst, const void* src) {
    asm volatile("cp.async.ca.shared.global [%0], [%1], 16;" :: "r"(dst), "l"(src));
}
__device__ __forceinline__ void cp_commit() {
    asm volatile("cp.async.commit_group;" ::: "memory");
}
template <int NW>
__device__ __forceinline__ void cp_wait() {
    asm volatile("cp.async.wait_group %0;" :: "n"(NW) : "memory");
}
// XOR swizzle for [rows][128] bf16 arrays (256 B/row): byte offset
__device__ __forceinline__ int swz(int row, int col) {
    return row * 256 + ((((col >> 3) ^ (row & 7)) << 4) | ((col & 7) << 1));
}

// ---------------- adjacency normalization ----------------
__global__ void adj_rowsum_k(const float* __restrict__ adj, float* __restrict__ dis) {
    int i = threadIdx.x;
    float s = 1.0f;
    for (int j = 0; j < N_; j++) s += adj[i * N_ + j];
    dis[i] = (s > 0.0f) ? rsqrtf(s) : 0.0f;
}
__global__ void adj_norm_k(const float* __restrict__ adj, const float* __restrict__ dis,
                           float* __restrict__ out,
                           __nv_bfloat16* __restrict__ ohi, __nv_bfloat16* __restrict__ olo) {
    int j = blockIdx.x * blockDim.x + threadIdx.x;
    int i = blockIdx.y;
    float a = adj[i * N_ + j] + (i == j ? 1.0f : 0.0f);
    float v = dis[i] * a * dis[j];
    out[i * N_ + j] = v;
    __nv_bfloat16 h = __float2bfloat16(v);
    ohi[i * N_ + j] = h;
    olo[i * N_ + j] = __float2bfloat16(v - __bfloat162float(h));
}

// ---------------- elementwise fp32 -> bf16 hi/lo split ----------------
__global__ void split_k(const float* __restrict__ src, __nv_bfloat16* __restrict__ hi,
                        __nv_bfloat16* __restrict__ lo, int n) {
    int i = blockIdx.x * blockDim.x + threadIdx.x;
    if (i >= n) return;
    float v = src[i];
    __nv_bfloat16 h = __float2bfloat16(v);
    hi[i] = h;
    lo[i] = __float2bfloat16(v - __bfloat162float(h));
}

// ---------------- transpose + split: S1[b][node][c] -> S1T[b][c][node] bf16 hi/lo ----------------
__global__ void transpose_split_k(const float* __restrict__ src,
                                  __nv_bfloat16* __restrict__ hi, __nv_bfloat16* __restrict__ lo) {
    __shared__ float tile[32][33];
    const int b = blockIdx.z;
    const long long cBase = (long long)blockIdx.x * 32;
    const long long nBase = (long long)blockIdx.y * 32;
    const float* s = src + (long long)b * N_ * (T_ * H_);
    #pragma unroll
    for (int i = threadIdx.y; i < 32; i += 8)
        tile[i][threadIdx.x] = s[(nBase + i) * (T_ * H_) + cBase + threadIdx.x];
    __syncthreads();
    const long long ob = (long long)b * (T_ * H_) * N_;
    #pragma unroll
    for (int i = threadIdx.y; i < 32; i += 8) {
        float v = tile[threadIdx.x][i];
        __nv_bfloat16 h = __float2bfloat16(v);
        long long o = ob + (cBase + i) * N_ + nBase + threadIdx.x;
        hi[o] = h;
        lo[o] = __float2bfloat16(v - __bfloat162float(h));
    }
}

// ---------------- tiled fp32 GEMM with FFMA2 (SIMT; steps 2,3,4, FC) ----------------
template <int BM, int BN, int BK, int TM, int TN, bool TRANSB, bool MASKB, bool RELU, bool BIAS>
__global__ void __launch_bounds__((BM / TM) * (BN / TN))
gemm_k(const float* __restrict__ A, const float* __restrict__ B,
       const float* __restrict__ bias, float* __restrict__ C,
       int M, int N, int K, long long sB, long long sC, int bias_mod) {
    constexpr int THREADS = (BM / TM) * (BN / TN);
    constexpr int MCH = TM / 4, NCH = TN / 4;
    constexpr int RS = BM / MCH, CS = BN / NCH;

    B += (long long)blockIdx.z * sB;
    C += (long long)blockIdx.z * sC;

    __shared__ float As[BK][BM + 4];
    __shared__ float Bs[BK][BN + 4];

    const int tid   = threadIdx.x;
    const int tcols = BN / TN;
    const int trow  = tid / tcols;
    const int tcol  = tid % tcols;
    const long long row0 = (long long)blockIdx.y * BM;
    const int col0 = blockIdx.x * BN;

    u64_t acc[TM][TN / 2];
    #pragma unroll
    for (int m = 0; m < TM; m++)
        #pragma unroll
        for (int p = 0; p < TN / 2; p++) acc[m][p] = 0ULL;

    for (int k0 = 0; k0 < K; k0 += BK) {
        #pragma unroll
        for (int i = tid; i < BM * BK / 4; i += THREADS) {
            int r = i / (BK / 4), kk = (i % (BK / 4)) * 4;
            float4 v = *(const float4*)&A[(row0 + r) * K + k0 + kk];
            As[kk + 0][r] = v.x; As[kk + 1][r] = v.y;
            As[kk + 2][r] = v.z; As[kk + 3][r] = v.w;
        }
        if (!TRANSB) {
            #pragma unroll
            for (int i = tid; i < BK * BN / 4; i += THREADS) {
                int r = i / (BN / 4), c = (i % (BN / 4)) * 4;
                float4 v = *(const float4*)&B[(long long)(k0 + r) * N + col0 + c];
                if (MASKB) {
                    if (v.x == -1.0f) v.x = 0.0f;
                    if (v.y == -1.0f) v.y = 0.0f;
                    if (v.z == -1.0f) v.z = 0.0f;
                    if (v.w == -1.0f) v.w = 0.0f;
                }
                *(float4*)&Bs[r][c] = v;
            }
        } else {
            #pragma unroll
            for (int i = tid; i < BN * BK / 4; i += THREADS) {
                int c = i / (BK / 4), kk = (i % (BK / 4)) * 4;
                float4 v = *(const float4*)&B[(long long)(col0 + c) * K + k0 + kk];
                Bs[kk + 0][c] = v.x; Bs[kk + 1][c] = v.y;
                Bs[kk + 2][c] = v.z; Bs[kk + 3][c] = v.w;
            }
        }
        __syncthreads();

        #pragma unroll 4
        for (int k = 0; k < BK; k++) {
            u64_t av[TM];
            #pragma unroll
            for (int i = 0; i < MCH; i++) {
                float4 a = *(const float4*)&As[k][i * RS + trow * 4];
                av[i * 4 + 0] = bcast2(a.x); av[i * 4 + 1] = bcast2(a.y);
                av[i * 4 + 2] = bcast2(a.z); av[i * 4 + 3] = bcast2(a.w);
            }
            u64_t bp[TN / 2];
            #pragma unroll
            for (int j = 0; j < NCH; j++) {
                float4 b = *(const float4*)&Bs[k][j * CS + tcol * 4];
                bp[j * 2 + 0] = lo2(b);
                bp[j * 2 + 1] = hi2(b);
            }
            #pragma unroll
            for (int m = 0; m < TM; m++)
                #pragma unroll
                for (int p = 0; p < TN / 2; p++)
                    fma2(acc[m][p], av[m], bp[p]);
        }
        __syncthreads();
    }

    #pragma unroll
    for (int i = 0; i < MCH; i++) {
        #pragma unroll
        for (int mm = 0; mm < 4; mm++) {
            long long row = row0 + i * RS + trow * 4 + mm;
            int m = i * 4 + mm;
            #pragma unroll
            for (int j = 0; j < NCH; j++) {
                int col = col0 + j * CS + tcol * 4;
                float2 lo = unpack2(acc[m][j * 2]);
                float2 hi = unpack2(acc[m][j * 2 + 1]);
                float4 v = make_float4(lo.x, lo.y, hi.x, hi.y);
                if (BIAS) {
                    int cb = col % bias_mod;
                    v.x += bias[cb]; v.y += bias[cb + 1];
                    v.z += bias[cb + 2]; v.w += bias[cb + 3];
                }
                if (RELU) {
                    v.x = fmaxf(v.x, 0.f); v.y = fmaxf(v.y, 0.f);
                    v.z = fmaxf(v.z, 0.f); v.w = fmaxf(v.w, 0.f);
                }
                *(float4*)&C[row * N + col] = v;
            }
        }
    }
}

// ---------------- split-bf16 tensor-core GEMM via mma.sync + cp.async 2-stage ----------------
constexpr int MMA_ARR  = 128 * 40;
constexpr int MMA_STAGE = 4 * MMA_ARR;
constexpr int MMA_SMEM = 2 * MMA_STAGE * 2;        // 81920 bytes

template <bool SPLIT_OUT>
__global__ void __launch_bounds__(256)
mma_gemm_k(const __nv_bfloat16* __restrict__ Ahi, const __nv_bfloat16* __restrict__ Alo,
           long long lda,
           const __nv_bfloat16* __restrict__ Bhi, const __nv_bfloat16* __restrict__ Blo,
           long long ldb, long long bzRows,
           const float* __restrict__ bias, int bias_mod,
           float* __restrict__ Dout,
           __nv_bfloat16* __restrict__ DhiOut, __nv_bfloat16* __restrict__ DloOut,
           long long ldd, long long dz, int K) {
    extern __shared__ __align__(16) __nv_bfloat16 smem[];

    const int tid = threadIdx.x, wid = tid >> 5, lane = tid & 31;
    const int wm = wid >> 1, wn = wid & 1;
    const long long z = blockIdx.z;
    const long long aRow0 = (long long)blockIdx.y * 128;
    const long long bRow0 = (long long)blockIdx.x * 128 + z * bzRows;

    const __nv_bfloat16* srcs[4] = {Ahi + aRow0 * lda, Alo + aRow0 * lda,
                                    Bhi + bRow0 * ldb, Blo + bRow0 * ldb};
    const long long lds[4] = {lda, lda, ldb, ldb};

    const int e0 = tid, e1 = tid + 256;
    const int r0c = e0 >> 2, q0c = e0 & 3;
    const int r1c = e1 >> 2, q1c = e1 & 3;

    auto load_stage = [&](int stage, int kc) {
        #pragma unroll
        for (int arr = 0; arr < 4; arr++) {
            __nv_bfloat16* dst = smem + stage * MMA_STAGE + arr * MMA_ARR;
            cp16(smem_u32(dst + r0c * 40 + q0c * 8),
                 srcs[arr] + (long long)r0c * lds[arr] + kc + q0c * 8);
            cp16(smem_u32(dst + r1c * 40 + q1c * 8),
                 srcs[arr] + (long long)r1c * lds[arr] + kc + q1c * 8);
        }
        cp_commit();
    };

    float acc[2][8][4];
    #pragma unroll
    for (int mf = 0; mf < 2; mf++)
        #pragma unroll
        for (int nf = 0; nf < 8; nf++)
            #pragma unroll
            for (int q = 0; q < 4; q++) acc[mf][nf][q] = 0.0f;

    const int a_r  = lane & 15;
    const int a_c8 = (lane >> 4) << 3;
    const int b_r  = lane & 7;
    const int b_c8 = ((lane >> 3) & 1) << 3;

    const int nk = K >> 5;
    load_stage(0, 0);

    for (int i = 0; i < nk; i++) {
        const int stage = i & 1;
        if (i + 1 < nk) {
            load_stage(stage ^ 1, (i + 1) << 5);
            cp_wait<1>();
        } else {
            cp_wait<0>();
        }
        __syncthreads();

        const __nv_bfloat16* sAhi = smem + stage * MMA_STAGE + 0 * MMA_ARR;
        const __nv_bfloat16* sAlo = smem + stage * MMA_STAGE + 1 * MMA_ARR;
        const __nv_bfloat16* sBhi = smem + stage * MMA_STAGE + 2 * MMA_ARR;
        const __nv_bfloat16* sBlo = smem + stage * MMA_STAGE + 3 * MMA_ARR;

        #pragma unroll
        for (int ks = 0; ks < 2; ks++) {
            const int kk = ks * 16;
            uint32_t ahi[2][4], alo[2][4];
            #pragma unroll
            for (int mf = 0; mf < 2; mf++) {
                int row = wm * 32 + mf * 16 + a_r;
                ldm_x4(ahi[mf][0], ahi[mf][1], ahi[mf][2], ahi[mf][3],
                       smem_u32(sAhi + row * 40 + kk + a_c8));
                ldm_x4(alo[mf][0], alo[mf][1], alo[mf][2], alo[mf][3],
                       smem_u32(sAlo + row * 40 + kk + a_c8));
            }
            #pragma unroll
            for (int nf = 0; nf < 8; nf++) {
                int n = wn * 64 + nf * 8 + b_r;
                uint32_t bhi[2], blo[2];
                ldm_x2(bhi[0], bhi[1], smem_u32(sBhi + n * 40 + kk + b_c8));
                ldm_x2(blo[0], blo[1], smem_u32(sBlo + n * 40 + kk + b_c8));
                #pragma unroll
                for (int mf = 0; mf < 2; mf++) {
                    mma_bf16(acc[mf][nf], ahi[mf], bhi);
                    mma_bf16(acc[mf][nf], ahi[mf], blo);
                    mma_bf16(acc[mf][nf], alo[mf], bhi);
                }
            }
        }
        __syncthreads();
    }

    const int colBlk = blockIdx.x * 128;
    #pragma unroll
    for (int mf = 0; mf < 2; mf++) {
        #pragma unroll
        for (int nf = 0; nf < 8; nf++) {
            int col = colBlk + wn * 64 + nf * 8 + (lane & 3) * 2;
            int cb = col % bias_mod;
            float bb0 = bias[cb], bb1 = bias[cb + 1];
            long long r0 = aRow0 + wm * 32 + mf * 16 + (lane >> 2);
            #pragma unroll
            for (int h = 0; h < 2; h++) {
                long long row = r0 + h * 8;
                float v0 = acc[mf][nf][h * 2 + 0] + bb0;
                float v1 = acc[mf][nf][h * 2 + 1] + bb1;
                long long o = z * dz + row * ldd + col;
                if (SPLIT_OUT) {
                    v0 = fmaxf(v0, 0.0f); v1 = fmaxf(v1, 0.0f);
                    __nv_bfloat16 h0 = __float2bfloat16(v0);
                    __nv_bfloat16 h1 = __float2bfloat16(v1);
                    __nv_bfloat162 hv; hv.x = h0; hv.y = h1;
                    __nv_bfloat162 lv;
                    lv.x = __float2bfloat16(v0 - __bfloat162float(h0));
                    lv.y = __float2bfloat16(v1 - __bfloat162float(h1));
                    *(__nv_bfloat162*)(DhiOut + o) = hv;
                    *(__nv_bfloat162*)(DloOut + o) = lv;
                } else {
                    float2 fv; fv.x = v0; fv.y = v1;
                    *(float2*)(Dout + o) = fv;
                }
            }
        }
    }
}

// ---------------- fused persistent GRU with tensor-core recurrence ----------------
// ks-loop deliberately NOT unrolled (compile-cost hedge; body is ~100 asm ops).
constexpr int GRU_SMEM = 229376;

__global__ void __launch_bounds__(256, 1)
gru_mma_k(const float* __restrict__ gi, const float* __restrict__ w_hh,
          const float* __restrict__ b_hh, float* __restrict__ out) {
    extern __shared__ __align__(16) char gsm[];
    char* whh_hi = gsm;                  // 98304 B
    char* whh_lo = gsm + 98304;          // 98304 B
    char* h_hi   = gsm + 196608;         // 16384 B
    char* h_lo   = gsm + 212992;         // 16384 B

    const int tid = threadIdx.x, wid = tid >> 5, lane = tid & 31;
    const int wm = wid >> 2, wn = wid & 3;
    const long long bn0 = (long long)blockIdx.x * 64;

    for (int i = tid; i < 384 * 128; i += 256) {
        int n = i >> 7, c = i & 127;
        float v = w_hh[i];
        __nv_bfloat16 hh = __float2bfloat16(v);
        int off = swz(n, c);
        *(__nv_bfloat16*)(whh_hi + off) = hh;
        *(__nv_bfloat16*)(whh_lo + off) = __float2bfloat16(v - __bfloat162float(hh));
    }
    for (int i = tid * 4; i < 16384; i += 1024) {
        *(uint32_t*)(h_hi + i) = 0;
        *(uint32_t*)(h_lo + i) = 0;
    }

    float bh[3][4][2];
    #pragma unroll
    for (int g = 0; g < 3; g++)
        #pragma unroll
        for (int nf = 0; nf < 4; nf++) {
            int c = g * 128 + wn * 32 + nf * 8 + (lane & 3) * 2;
            bh[g][nf][0] = b_hh[c];
            bh[g][nf][1] = b_hh[c + 1];
        }

    float hreg[2][4][2][2];
    #pragma unroll
    for (int mf = 0; mf < 2; mf++)
        #pragma unroll
        for (int nf = 0; nf < 4; nf++) {
            hreg[mf][nf][0][0] = 0.f; hreg[mf][nf][0][1] = 0.f;
            hreg[mf][nf][1][0] = 0.f; hreg[mf][nf][1][1] = 0.f;
        }
    __syncthreads();

    const int a_r = lane & 15, a_c8 = (lane >> 4) << 3;
    const int b_g = lane >> 3, b_ln = lane & 7;
    const int b_rowadd = ((b_g >> 1) << 3) + b_ln;
    const int b_kadd = (b_g & 1) << 3;

    for (int t = 0; t < T_; t++) {
        float acc[2][3][4][4];
        #pragma unroll
        for (int mf = 0; mf < 2; mf++)
            #pragma unroll
            for (int g = 0; g < 3; g++)
                #pragma unroll
                for (int nf = 0; nf < 4; nf++) {
                    acc[mf][g][nf][0] = 0.f; acc[mf][g][nf][1] = 0.f;
                    acc[mf][g][nf][2] = 0.f; acc[mf][g][nf][3] = 0.f;
                }

        #pragma unroll 1
        for (int ks = 0; ks < 8; ks++) {
            const int kk = ks * 16;
            uint32_t ahi[2][4], alo[2][4];
            #pragma unroll
            for (int mf = 0; mf < 2; mf++) {
                int row = wm * 32 + mf * 16 + a_r;
                ldm_x4(ahi[mf][0], ahi[mf][1], ahi[mf][2], ahi[mf][3],
                       smem_u32(h_hi + swz(row, kk + a_c8)));
                ldm_x4(alo[mf][0], alo[mf][1], alo[mf][2], alo[mf][3],
                       smem_u32(h_lo + swz(row, kk + a_c8)));
            }
            #pragma unroll
            for (int g = 0; g < 3; g++) {
                #pragma unroll
                for (int p = 0; p < 2; p++) {
                    int rowb = g * 128 + wn * 32 + p * 16 + b_rowadd;
                    int kcol = kk + b_kadd;
                    uint32_t bhr[4], blr[4];
                    ldm_x4(bhr[0], bhr[1], bhr[2], bhr[3],
                           smem_u32(whh_hi + swz(rowb, kcol)));
                    ldm_x4(blr[0], blr[1], blr[2], blr[3],
                           smem_u32(whh_lo + swz(rowb, kcol)));
                    #pragma unroll
                    for (int q = 0; q < 2; q++) {
                        int nf = p * 2 + q;
                        uint32_t bh2[2] = {bhr[q * 2], bhr[q * 2 + 1]};
                        uint32_t bl2[2] = {blr[q * 2], blr[q * 2 + 1]};
                        #pragma unroll
                        for (int mf = 0; mf < 2; mf++) {
                            mma_bf16(acc[mf][g][nf], ahi[mf], bh2);
                            mma_bf16(acc[mf][g][nf], ahi[mf], bl2);
                            mma_bf16(acc[mf][g][nf], alo[mf], bh2);
                        }
                    }
                }
            }
        }
        __syncthreads();

        #pragma unroll
        for (int mf = 0; mf < 2; mf++) {
            #pragma unroll
            for (int nf = 0; nf < 4; nf++) {
                #pragma unroll
                for (int hh = 0; hh < 2; hh++) {
                    int m = wm * 32 + mf * 16 + (lane >> 2) + hh * 8;
                    long long rg = bn0 + m;
                    int c = wn * 32 + nf * 8 + (lane & 3) * 2;
                    const float* gp = gi + (rg * T_ + t) * 384 + c;
                    float2 xr = *(const float2*)gp;
                    float2 xz = *(const float2*)(gp + 128);
                    float2 xn = *(const float2*)(gp + 256);
                    float rr0 = sigmoid_fast(xr.x + acc[mf][0][nf][hh * 2]     + bh[0][nf][0]);
                    float rr1 = sigmoid_fast(xr.y + acc[mf][0][nf][hh * 2 + 1] + bh[0][nf][1]);
                    float zz0 = sigmoid_fast(xz.x + acc[mf][1][nf][hh * 2]     + bh[1][nf][0]);
                    float zz1 = sigmoid_fast(xz.y + acc[mf][1][nf][hh * 2 + 1] + bh[1][nf][1]);
                    float nn0 = tanh_fast(xn.x + rr0 * (acc[mf][2][nf][hh * 2]     + bh[2][nf][0]));
                    float nn1 = tanh_fast(xn.y + rr1 * (acc[mf][2][nf][hh * 2 + 1] + bh[2][nf][1]));
                    float hp0 = hreg[mf][nf][hh][0], hp1 = hreg[mf][nf][hh][1];
                    float h0 = fmaf(zz0, hp0 - nn0, nn0);
                    float h1 = fmaf(zz1, hp1 - nn1, nn1);
                    hreg[mf][nf][hh][0] = h0; hreg[mf][nf][hh][1] = h1;

                    float2 o; o.x = h0; o.y = h1;
                    *(float2*)(out + (rg * T_ + t) * 128 + c) = o;

                    __nv_bfloat16 c0 = __float2bfloat16(h0);
                    __nv_bfloat16 c1 = __float2bfloat16(h1);
                    __nv_bfloat162 hv; hv.x = c0; hv.y = c1;
                    __nv_bfloat162 lv;
                    lv.x = __float2bfloat16(h0 - __bfloat162float(c0));
                    lv.y = __float2bfloat16(h1 - __bfloat162float(c1));
                    int off = swz(m, c);
                    *(__nv_bfloat162*)(h_hi + off) = hv;
                    *(__nv_bfloat162*)(h_lo + off) = lv;
                }
            }
        }
        __syncthreads();
    }
}

// ---------------- launch ----------------
extern "C" void kernel_launch(void* const* d_in, const int* in_sizes, int n_in,
                              void* d_out, int out_size) {
    const float* x     = (const float*)d_in[0];
    const float* adj   = (const float*)d_in[1];
    const float* gc_w0 = (const float*)d_in[2];
    const float* gc_b0 = (const float*)d_in[3];
    const float* gc_w1 = (const float*)d_in[4];
    const float* gc_b1 = (const float*)d_in[5];
    const float* w_ih  = (const float*)d_in[6];
    const float* w_hh  = (const float*)d_in[7];
    const float* b_ih  = (const float*)d_in[8];
    const float* b_hh  = (const float*)d_in[9];
    const float* w_fc  = (const float*)d_in[10];
    const float* b_fc  = (const float*)d_in[11];
    float* out = (float*)d_out;

    unsigned char* pool;
    float *adjn, *dis;
    __nv_bfloat16 *adjn_hi, *adjn_lo, *wih_hi, *wih_lo;
    cudaGetSymbolAddress((void**)&pool,    g_pool);
    cudaGetSymbolAddress((void**)&adjn,    g_adjn);
    cudaGetSymbolAddress((void**)&adjn_hi, g_adjn_hi);
    cudaGetSymbolAddress((void**)&adjn_lo, g_adjn_lo);
    cudaGetSymbolAddress((void**)&dis,     g_dis);
    cudaGetSymbolAddress((void**)&wih_hi,  g_wih_hi);
    cudaGetSymbolAddress((void**)&wih_lo,  g_wih_lo);

    __nv_bfloat16* s1t_hi = (__nv_bfloat16*)(pool + 0);
    __nv_bfloat16* s1t_lo = (__nv_bfloat16*)(pool + 201326592ULL);
    float*         h1     = (float*)(pool + 402653184ULL);
    float*         s1     = (float*)(pool + 805306368ULL);   // also Y0
    float*         gi     = (float*)(pool + 0);
    __nv_bfloat16* h2_hi  = (__nv_bfloat16*)(pool + 1207959552ULL);
    __nv_bfloat16* h2_lo  = (__nv_bfloat16*)(pool + 1409286144ULL);
    float*         gru_o  = (float*)(pool + 1207959552ULL);

    const int M = (int)M_TOT;   // 786432

    // 1) adjacency normalization (+ bf16 split) and w_ih split
    adj_rowsum_k<<<1, N_>>>(adj, dis);
    adj_norm_k<<<dim3(N_ / 256, N_), 256>>>(adj, dis, adjn, adjn_hi, adjn_lo);
    split_k<<<(3 * H_ * H_ + 255) / 256, 256>>>(w_ih, wih_hi, wih_lo, 3 * H_ * H_);

    // 2) A-hop on raw (masked) x: Y0 = adjn @ mask(x)   (SIMT)
    gemm_k<128, 128, 16, 8, 8, false, true, false, false>
        <<<dim3((T_ * FIN_) / 128, N_ / 128, B_), 256>>>(
            adjn, x, nullptr, s1 /*Y0*/, N_, T_ * FIN_, N_,
            (long long)N_ * T_ * FIN_, (long long)N_ * T_ * FIN_, 1);

    // 3) h1 = relu(Y0 @ gc_w0 + b0)  (SIMT)
    gemm_k<128, 128, 16, 8, 8, false, false, true, true>
        <<<dim3(1, M / 128), 256>>>(s1 /*Y0*/, gc_w0, gc_b0, h1,
                                    M, H_, FIN_, 0, 0, H_);

    // 4) S1 = h1 @ gc_w1  (SIMT, fp32)
    gemm_k<128, 128, 16, 8, 8, false, false, false, false>
        <<<dim3(1, M / 128), 256>>>(h1, gc_w1, nullptr, s1,
                                    M, H_, H_, 0, 0, 1);

    // 4b) transpose + split: S1 -> S1T bf16 hi/lo
    transpose_split_k<<<dim3((T_ * H_) / 32, N_ / 32, B_), dim3(32, 8)>>>(s1, s1t_hi, s1t_lo);

    // 5) h2 = relu(adjn @ S1 + b1)  (mma.sync + cp.async)
    cudaFuncSetAttribute(mma_gemm_k<true>,  cudaFuncAttributeMaxDynamicSharedMemorySize, MMA_SMEM);
    cudaFuncSetAttribute(mma_gemm_k<false>, cudaFuncAttributeMaxDynamicSharedMemorySize, MMA_SMEM);
    mma_gemm_k<true><<<dim3((T_ * H_) / 128, N_ / 128, B_), 256, MMA_SMEM>>>(
        adjn_hi, adjn_lo, N_,
        s1t_hi, s1t_lo, N_, (long long)T_ * H_,
        gc_b1, H_,
        nullptr, h2_hi, h2_lo,
        (long long)T_ * H_, (long long)N_ * T_ * H_, N_);

    // 6) GI = h2 @ w_ih^T + b_ih  (mma.sync + cp.async)
    mma_gemm_k<false><<<dim3((3 * H_) / 128, M / 128, 1), 256, MMA_SMEM>>>(
        h2_hi, h2_lo, H_,
        wih_hi, wih_lo, H_, 0,
        b_ih, 3 * H_,
        gi, nullptr, nullptr,
        3 * H_, 0, H_);

    // 7) fused GRU recurrence, tensor-core gh (single persistent launch)
    cudaFuncSetAttribute(gru_mma_k, cudaFuncAttributeMaxDynamicSharedMemorySize, GRU_SMEM);
    gru_mma_k<<<BN_TOT / 64, 256, GRU_SMEM>>>(gi, w_hh, b_hh, gru_o);

    // 8) FC: out = gru_out @ w_fc + b_fc  (SIMT)
    gemm_k<128, 32, 16, 8, 4, false, false, false, true>
        <<<dim3(1, M / 128), 128>>>(gru_o, w_fc, b_fc, out,
                                    M, FOUT_, H_, 0, 0, FOUT_);
}